// round 11
// baseline (speedup 1.0000x reference)
#include <cuda_runtime.h>
#include <cuda_bf16.h>
#include <math.h>
#include <stdint.h>

typedef __nv_bfloat16 bf16;

#define BATCH   16
#define C_DIM   384
#define NPIX    784
#define T_TOK   (BATCH*NPIX)      // 12544
#define HEADS   8
#define HDIM    48
#define FFN_DIM 1536
#define BN_EPS  1e-5f

// ---------------- scratch (static device globals; no allocation) ----------------
__device__ float g_lx [T_TOK*C_DIM];        // token-major f32 (residual for proj)
__device__ bf16  g_lxh[T_TOK*C_DIM];
__device__ bf16  g_lxl[T_TOK*C_DIM];
__device__ bf16  g_qh [T_TOK*C_DIM];        // Q (scale folded) hi/lo, [t][c]
__device__ bf16  g_ql [T_TOK*C_DIM];
__device__ bf16  g_kh [T_TOK*C_DIM];        // K hi/lo, [t][c]
__device__ bf16  g_kl [T_TOK*C_DIM];
__device__ bf16  g_vth[T_TOK*C_DIM + 64];   // V^T hi/lo, [b][h][d][n] (+pad for tail overread)
__device__ bf16  g_vtl[T_TOK*C_DIM + 64];
__device__ bf16  g_aoh[T_TOK*C_DIM];        // attention out hi/lo
__device__ bf16  g_aol[T_TOK*C_DIM];
__device__ float g_r  [T_TOK*C_DIM];        // residual (proj + lx), f32
__device__ bf16  g_hh [T_TOK*C_DIM];        // bn2(residual) hi/lo
__device__ bf16  g_hl [T_TOK*C_DIM];
__device__ bf16  g_f1h[T_TOK*FFN_DIM];      // ffn1 output hi/lo
__device__ bf16  g_f1l[T_TOK*FFN_DIM];
// weights hi/lo
__device__ bf16  g_qwh[C_DIM*C_DIM], g_qwl[C_DIM*C_DIM];
__device__ bf16  g_kwh[C_DIM*C_DIM], g_kwl[C_DIM*C_DIM];
__device__ bf16  g_vwh[C_DIM*C_DIM], g_vwl[C_DIM*C_DIM];
__device__ bf16  g_pwh[C_DIM*C_DIM], g_pwl[C_DIM*C_DIM];
__device__ bf16  g_w1h[FFN_DIM*C_DIM], g_w1l[FFN_DIM*C_DIM];
__device__ bf16  g_w2h[C_DIM*FFN_DIM], g_w2l[C_DIM*FFN_DIM];

// ======================= helpers =======================
__device__ __forceinline__ uint32_t smem_u32(const void* p) {
    return (uint32_t)__cvta_generic_to_shared(p);
}
__device__ __forceinline__ void split_bf16(float x, bf16& hi, bf16& lo) {
    hi = __float2bfloat16_rn(x);
    lo = __float2bfloat16_rn(x - __bfloat162float(hi));
}
__device__ __forceinline__ uint32_t pack_bf2(bf16 a, bf16 b) {
    __nv_bfloat162 t; t.x = a; t.y = b;
    return *reinterpret_cast<uint32_t*>(&t);
}
__device__ __forceinline__ void ldsm4(uint32_t* r, uint32_t addr) {
    asm volatile("ldmatrix.sync.aligned.m8n8.x4.shared.b16 {%0,%1,%2,%3}, [%4];"
                 : "=r"(r[0]), "=r"(r[1]), "=r"(r[2]), "=r"(r[3]) : "r"(addr));
}
__device__ __forceinline__ void mma16816(float* c, const uint32_t* a, uint32_t b0, uint32_t b1) {
    asm volatile("mma.sync.aligned.m16n8k16.row.col.f32.bf16.bf16.f32 "
                 "{%0,%1,%2,%3}, {%4,%5,%6,%7}, {%8,%9}, {%0,%1,%2,%3};"
                 : "+f"(c[0]), "+f"(c[1]), "+f"(c[2]), "+f"(c[3])
                 : "r"(a[0]), "r"(a[1]), "r"(a[2]), "r"(a[3]), "r"(b0), "r"(b1));
}
__device__ __forceinline__ void cp16(uint32_t dst, const void* src) {
    asm volatile("cp.async.cg.shared.global [%0], [%1], 16;" :: "r"(dst), "l"(src));
}
#define CP_COMMIT() asm volatile("cp.async.commit_group;")
#define CP_WAIT1()  asm volatile("cp.async.wait_group 1;")
#define CP_WAIT0()  asm volatile("cp.async.wait_group 0;")

// ---------------- merged f32 -> bf16 hi/lo conversion (all weights) ----------------
#define NW (C_DIM*C_DIM)       // 147456
#define NF (FFN_DIM*C_DIM)     // 589824
__global__ void cvt_all_kernel(
    const float* __restrict__ s0, bf16* __restrict__ h0, bf16* __restrict__ l0,
    const float* __restrict__ s1, bf16* __restrict__ h1, bf16* __restrict__ l1,
    const float* __restrict__ s2, bf16* __restrict__ h2, bf16* __restrict__ l2,
    const float* __restrict__ s3, bf16* __restrict__ h3, bf16* __restrict__ l3,
    const float* __restrict__ s4, bf16* __restrict__ h4, bf16* __restrict__ l4,
    const float* __restrict__ s5, bf16* __restrict__ h5, bf16* __restrict__ l5)
{
    int idx = blockIdx.x * 256 + threadIdx.x;
    const float* s; bf16 *h, *l; int off;
    if (idx < 4*NW) {
        int w = idx / NW; off = idx - w*NW;
        s = (w==0) ? s0 : (w==1) ? s1 : (w==2) ? s2 : s3;
        h = (w==0) ? h0 : (w==1) ? h1 : (w==2) ? h2 : h3;
        l = (w==0) ? l0 : (w==1) ? l1 : (w==2) ? l2 : l3;
    } else {
        int i2 = idx - 4*NW;
        if (i2 < NF)            { s = s4; h = h4; l = l4; off = i2; }
        else if (i2 < 2*NF)     { s = s5; h = h5; l = l5; off = i2 - NF; }
        else return;
    }
    bf16 hi, lo; split_bf16(s[off], hi, lo); h[off] = hi; l[off] = lo;
}

// ---------------- fused depthwise 3x3 conv + BN1 + transpose -> token-major ----------------
__global__ void conv_tokens_kernel(const float* __restrict__ x,
                                   const float* __restrict__ w,
                                   const float* __restrict__ bconv,
                                   const float* __restrict__ bg,
                                   const float* __restrict__ bb,
                                   const float* __restrict__ bm,
                                   const float* __restrict__ bv)
{
    __shared__ float tile[32][33];
    int b   = blockIdx.z;
    int hw0 = blockIdx.x * 32;
    int c0  = blockIdx.y * 32;
    int tx = threadIdx.x, ty = threadIdx.y;   // 32 x 8
#pragma unroll
    for (int j = 0; j < 32; j += 8) {
        int c = c0 + ty + j, hw = hw0 + tx;
        float val = 0.f;
        if (hw < NPIX) {
            int yy = hw / 28, xx = hw % 28;
            const float* xp = x + ((size_t)b*C_DIM + c) * NPIX;
            const float* wp = w + c * 9;
            float s = 0.f;
#pragma unroll
            for (int ky = 0; ky < 3; ky++) {
                int y = yy + ky - 1;
                if ((unsigned)y < 28u) {
#pragma unroll
                    for (int kx = 0; kx < 3; kx++) {
                        int x2 = xx + kx - 1;
                        if ((unsigned)x2 < 28u) s += wp[ky*3+kx] * xp[y*28 + x2];
                    }
                }
            }
            s += bconv[c];
            float inv = rsqrtf(bv[c] + BN_EPS);
            val = (s - bm[c]) * inv * bg[c] + bb[c];
        }
        tile[ty + j][tx] = val;
    }
    __syncthreads();
#pragma unroll
    for (int j = 0; j < 32; j += 8) {
        int hw = hw0 + ty + j, c = c0 + tx;
        if (hw < NPIX) {
            float v = tile[tx][ty + j];
            size_t idx = ((size_t)b*NPIX + hw)*C_DIM + c;
            g_lx[idx] = v;
            bf16 hi, lo; split_bf16(v, hi, lo);
            g_lxh[idx] = hi; g_lxl[idx] = lo;
        }
    }
}

// ======================= cp.async double-buffered split-bf16 GEMM =======================
// D[t][o] = sum_k A[t][k]*W[o][k], A=Ah+Al, W=Wh+Wl (3 MMAs: hh, hl, lh)
// CTA tile 256x128, 8 warps 4(m)x2(n), warp tile 64x64. K chunk 32, 2 stages.
// 96 MMA per 16 ldsm4 per K=16 step -> 85 B smem per MMA (was 128).
#define TM    256
#define TN    128
#define KC    32
#define ASTR  40                             // bf16 row stride; (r*20 mod 32) hits all banks
#define A_TILE_ELE (TM*ASTR)                 // 10240
#define W_TILE_ELE (TN*ASTR)                 // 5120
#define A_TILE_B (A_TILE_ELE*2)              // 20480 B
#define W_TILE_B (W_TILE_ELE*2)              // 10240 B
#define STAGE_B  (2*A_TILE_B + 2*W_TILE_B)   // 61440 B
#define GEMM_SMEM (2*STAGE_B)                // 122880 B

__device__ __forceinline__ void gemm_load_stage(
    const bf16* __restrict__ Ah, const bf16* __restrict__ Al,
    const bf16* __restrict__ Wh, const bf16* __restrict__ Wl,
    int t0, int o0, int K, int k0, uint32_t su)
{
    int tid = threadIdx.x;
#pragma unroll
    for (int i = 0; i < 4; ++i) {            // A: 256 rows x 4 chunks per type
        int ch = tid + i*256;                // 0..1023
        int r = ch >> 2, c = ch & 3;
        uint32_t d = (uint32_t)((r*ASTR + c*8) * 2);
        size_t so = (size_t)(t0 + r)*K + k0 + c*8;
        cp16(su + d,            Ah + so);
        cp16(su + A_TILE_B + d, Al + so);
    }
#pragma unroll
    for (int i = 0; i < 2; ++i) {            // W: 128 rows x 4 chunks per type
        int ch = tid + i*256;                // 0..511
        int r = ch >> 2, c = ch & 3;
        uint32_t d = (uint32_t)((r*ASTR + c*8) * 2);
        size_t so = (size_t)(o0 + r)*K + k0 + c*8;
        cp16(su + 2*A_TILE_B + d,            Wh + so);
        cp16(su + 2*A_TILE_B + W_TILE_B + d, Wl + so);
    }
    CP_COMMIT();
}

template<int MODE>
__global__ void __launch_bounds__(256, 1)
gemm_mma(const bf16* __restrict__ Ah, const bf16* __restrict__ Al,
         const bf16* __restrict__ Wh, const bf16* __restrict__ Wl,
         const float* __restrict__ bias, const float* __restrict__ res,
         const float* __restrict__ bng, const float* __restrict__ bnb,
         const float* __restrict__ bnm, const float* __restrict__ bnv,
         float* __restrict__ outf, bf16* __restrict__ oh, bf16* __restrict__ ol,
         int K, int N, float mult)
{
    extern __shared__ __align__(16) bf16 smb[];
    const uint32_t s0u = smem_u32(smb);

    const int tid = threadIdx.x;
    const int wid = tid >> 5, l = tid & 31;
    const int wm = wid & 3, wn = wid >> 2;    // warp tile: rows wm*64, cols wn*64
    const int t0 = blockIdx.y * TM;
    const int o0 = blockIdx.x * TN;

    float acc[4][8][4];
#pragma unroll
    for (int f = 0; f < 4; f++)
#pragma unroll
        for (int g = 0; g < 8; g++)
#pragma unroll
            for (int i = 0; i < 4; i++) acc[f][g][i] = 0.f;

    const int arow = l & 15;
    const int acol = (l >> 4) * 8;
    const int brow = ((l >> 4) << 3) + (l & 7);
    const int bcol = ((l >> 3) & 1) * 8;

    const int nch = K / KC;
    gemm_load_stage(Ah, Al, Wh, Wl, t0, o0, K, 0, s0u);

    for (int ch = 0; ch < nch; ++ch) {
        const int buf = ch & 1;
        __syncthreads();                               // stage buf^1 fully consumed
        if (ch + 1 < nch) {
            gemm_load_stage(Ah, Al, Wh, Wl, t0, o0, K, (ch+1)*KC,
                            s0u + (uint32_t)(buf ^ 1) * STAGE_B);
            CP_WAIT1();
        } else {
            CP_WAIT0();
        }
        __syncthreads();                               // stage buf visible to all

        const uint32_t sa = s0u + (uint32_t)buf * STAGE_B;
#pragma unroll
        for (int kk = 0; kk < 2; ++kk) {
            const int k0 = kk * 16;
            uint32_t ah[4][4], al2[4][4];
#pragma unroll
            for (int f = 0; f < 4; ++f) {
                uint32_t off = (uint32_t)(((wm*64 + f*16 + arow)*ASTR + k0 + acol) * 2);
                ldsm4(ah[f],  sa + off);
                ldsm4(al2[f], sa + A_TILE_B + off);
            }
#pragma unroll
            for (int gp = 0; gp < 4; ++gp) {
                uint32_t bh[4], bl[4];
                uint32_t off = (uint32_t)(((wn*64 + gp*16 + brow)*ASTR + k0 + bcol) * 2);
                ldsm4(bh, sa + 2*A_TILE_B + off);
                ldsm4(bl, sa + 2*A_TILE_B + W_TILE_B + off);
#pragma unroll
                for (int f = 0; f < 4; ++f) {
                    mma16816(acc[f][2*gp],   ah[f],  bh[0], bh[1]);
                    mma16816(acc[f][2*gp+1], ah[f],  bh[2], bh[3]);
                    mma16816(acc[f][2*gp],   ah[f],  bl[0], bl[1]);
                    mma16816(acc[f][2*gp+1], ah[f],  bl[2], bl[3]);
                    mma16816(acc[f][2*gp],   al2[f], bh[0], bh[1]);
                    mma16816(acc[f][2*gp+1], al2[f], bh[2], bh[3]);
                }
            }
        }
    }

    // ---- epilogue ----
    const int row_in = l >> 2, col_in = (l & 3) * 2;
#pragma unroll
    for (int f = 0; f < 4; ++f) {
        const int tb = t0 + wm*64 + f*16 + row_in;
#pragma unroll
        for (int g = 0; g < 8; ++g) {
            const int o = o0 + wn*64 + g*8 + col_in;
#pragma unroll
            for (int hhalf = 0; hhalf < 2; ++hhalf) {
                const int t = tb + hhalf*8;
                const float c0 = acc[f][g][hhalf*2 + 0];
                const float c1 = acc[f][g][hhalf*2 + 1];
                if (MODE == 0) {
                    float v0 = (c0 + bias[o]) * mult;
                    float v1 = (c1 + bias[o+1]) * mult;
                    bf16 h0, l0_, h1, l1_;
                    split_bf16(v0, h0, l0_); split_bf16(v1, h1, l1_);
                    *(uint32_t*)&oh[(size_t)t*N + o] = pack_bf2(h0, h1);
                    *(uint32_t*)&ol[(size_t)t*N + o] = pack_bf2(l0_, l1_);
                } else if (MODE == 1) {
#pragma unroll
                    for (int u = 0; u < 2; ++u) {
                        int oo = o + u;
                        size_t idx = (size_t)t*C_DIM + oo;
                        float val = (u ? c1 : c0) + bias[oo] + res[idx];
                        outf[idx] = val;
                        float inv = rsqrtf(bnv[oo] + BN_EPS);
                        float hb = (val - bnm[oo]) * inv * bng[oo] + bnb[oo];
                        bf16 hi, lo; split_bf16(hb, hi, lo);
                        oh[idx] = hi; ol[idx] = lo;
                    }
                } else if (MODE == 2) {
#pragma unroll
                    for (int u = 0; u < 2; ++u) {
                        int oo = o + u;
                        float val = (u ? c1 : c0) + bias[oo];
                        float ge = 0.5f * val * (1.0f + erff(val * 0.7071067811865475f));
                        size_t idx = (size_t)t*N + oo;
                        bf16 hi, lo; split_bf16(ge, hi, lo);
                        oh[idx] = hi; ol[idx] = lo;
                    }
                } else if (MODE == 3) { // NCHW final
                    const int bb2 = t / NPIX;
                    const int nn  = t - bb2 * NPIX;
#pragma unroll
                    for (int u = 0; u < 2; ++u) {
                        int oo = o + u;
                        float val = (u ? c1 : c0) + bias[oo] + res[(size_t)t*C_DIM + oo];
                        outf[((size_t)bb2*C_DIM + oo)*NPIX + nn] = val;
                    }
                } else { // MODE 4: V head-transposed [b][h][d][n]
                    const int bb2 = t / NPIX;
                    const int nn  = t - bb2 * NPIX;
#pragma unroll
                    for (int u = 0; u < 2; ++u) {
                        int oo = o + u;
                        int hh2 = oo / HDIM, dd = oo - hh2*HDIM;
                        float val = (u ? c1 : c0) + bias[oo];
                        bf16 hi, lo; split_bf16(val, hi, lo);
                        size_t dst = ((size_t)((bb2*HEADS + hh2)*HDIM + dd))*NPIX + nn;
                        oh[dst] = hi; ol[dst] = lo;
                    }
                }
            }
        }
    }
}

// ======================= flash-style mma attention (cp.async K/V pipeline) =======================
#define AQ_STR 56
#define AK_STR 56
#define AV_STR 72
#define K_STAGE_ELE (64*AK_STR)   // 3584
#define V_STAGE_ELE (48*AV_STR)   // 3456
// layout: Qh(7168) Ql(7168) | K stages [2][h,l] | V stages [2][h,l]
#define ATTN_SMEM ((2*128*AQ_STR + 4*K_STAGE_ELE + 4*V_STAGE_ELE) * 2)   // 84992 B
#define NBLK ((NPIX + 63) / 64)   // 13

__device__ __forceinline__ void attn_load_kv(
    const bf16* __restrict__ Kh, const bf16* __restrict__ Kl,
    const bf16* __restrict__ Vth, const bf16* __restrict__ Vtl,
    int b, int h, int n0,
    uint32_t kh_u, uint32_t kl_u, uint32_t vh_u, uint32_t vl_u)
{
    int tid = threadIdx.x;
    for (int idx = tid; idx < 64*6; idx += 256) {
        int r = idx / 6, cs = idx % 6;
        int t = b*NPIX + min(n0 + r, NPIX - 1);
        size_t so = (size_t)t*C_DIM + h*HDIM + cs*8;
        uint32_t d = (uint32_t)((r*AK_STR + cs*8) * 2);
        cp16(kh_u + d, Kh + so);
        cp16(kl_u + d, Kl + so);
    }
    for (int idx = tid; idx < 48*8; idx += 256) {
        int r = idx / 8, cs = idx % 8;
        size_t so = ((size_t)((b*HEADS + h)*HDIM + r))*NPIX + n0 + cs*8;
        uint32_t d = (uint32_t)((r*AV_STR + cs*8) * 2);
        cp16(vh_u + d, Vth + so);
        cp16(vl_u + d, Vtl + so);
    }
    CP_COMMIT();
}

__global__ void __launch_bounds__(256)
attn_mma(const bf16* __restrict__ Qh, const bf16* __restrict__ Ql,
         const bf16* __restrict__ Kh, const bf16* __restrict__ Kl,
         const bf16* __restrict__ Vth, const bf16* __restrict__ Vtl,
         bf16* __restrict__ AOh, bf16* __restrict__ AOl)
{
    extern __shared__ __align__(16) bf16 sm_[];
    bf16* sQh = sm_;
    bf16* sQl = sQh + 128*AQ_STR;
    bf16* sK  = sQl + 128*AQ_STR;      // [stage][h/l]
    bf16* sV  = sK + 4*K_STAGE_ELE;

    const int tid = threadIdx.x, w = tid >> 5, ln = tid & 31;
    const int qb = blockIdx.x, h = blockIdx.y, b = blockIdx.z;
    const int q0 = qb * 128;

    uint32_t kstage_u[2][2], vstage_u[2][2];
#pragma unroll
    for (int s = 0; s < 2; s++) {
        kstage_u[s][0] = smem_u32(sK + s*2*K_STAGE_ELE);
        kstage_u[s][1] = kstage_u[s][0] + K_STAGE_ELE*2;
        vstage_u[s][0] = smem_u32(sV + s*2*V_STAGE_ELE);
        vstage_u[s][1] = vstage_u[s][0] + V_STAGE_ELE*2;
    }

    // prefetch K/V block 0 while Q loads
    attn_load_kv(Kh, Kl, Vth, Vtl, b, h, 0, kstage_u[0][0], kstage_u[0][1],
                 vstage_u[0][0], vstage_u[0][1]);

    // ---- load Q tile (rows clamped to image) ----
    for (int idx = tid; idx < 128*6; idx += 256) {
        int r = idx / 6, cs = idx % 6;
        int t = b*NPIX + min(q0 + r, NPIX - 1);
        const bf16* ph_ = Qh + (size_t)t*C_DIM + h*HDIM;
        const bf16* pl_ = Ql + (size_t)t*C_DIM + h*HDIM;
        *(uint4*)(sQh + r*AQ_STR + cs*8) = *((const uint4*)ph_ + cs);
        *(uint4*)(sQl + r*AQ_STR + cs*8) = *((const uint4*)pl_ + cs);
    }
    __syncthreads();

    // ---- Q fragments (persistent) ----
    const int arow = ln & 15, acol = (ln >> 4) * 8;
    const int brow = ((ln >> 4) << 3) + (ln & 7), bcol = ((ln >> 3) & 1) * 8;
    uint32_t qfh[3][4], qfl[3][4];
    {
        const uint32_t qb_h = smem_u32(sQh), qb_l = smem_u32(sQl);
#pragma unroll
        for (int kc = 0; kc < 3; kc++) {
            uint32_t off = (uint32_t)(((w*16 + arow)*AQ_STR + kc*16 + acol) * 2);
            ldsm4(qfh[kc], qb_h + off);
            ldsm4(qfl[kc], qb_l + off);
        }
    }

    float rm0 = -1e30f, rm1 = -1e30f;   // running max (rows ln/4, ln/4+8)
    float rl0 = 0.f,    rl1 = 0.f;      // running sum
    float O[6][4];
#pragma unroll
    for (int j = 0; j < 6; j++)
#pragma unroll
        for (int i = 0; i < 4; i++) O[j][i] = 0.f;

    for (int it = 0; it < NBLK; ++it) {
        const int buf = it & 1;
        const int n0 = it * 64;
        __syncthreads();                            // stage buf^1 fully consumed
        if (it + 1 < NBLK) {
            attn_load_kv(Kh, Kl, Vth, Vtl, b, h, (it+1)*64,
                         kstage_u[buf^1][0], kstage_u[buf^1][1],
                         vstage_u[buf^1][0], vstage_u[buf^1][1]);
            CP_WAIT1();
        } else {
            CP_WAIT0();
        }
        __syncthreads();

        const uint32_t kb_h = kstage_u[buf][0], kb_l = kstage_u[buf][1];
        const uint32_t vb_h = vstage_u[buf][0], vb_l = vstage_u[buf][1];

        // ---- S = Q K^T (8 n-tiles of 8 keys) ----
        float s[8][4];
#pragma unroll
        for (int j = 0; j < 8; j++)
#pragma unroll
            for (int i = 0; i < 4; i++) s[j][i] = 0.f;

#pragma unroll
        for (int kc = 0; kc < 3; kc++) {
#pragma unroll
            for (int g = 0; g < 4; g++) {
                uint32_t off = (uint32_t)(((g*16 + brow)*AK_STR + kc*16 + bcol) * 2);
                uint32_t kh4[4], kl4[4];
                ldsm4(kh4, kb_h + off);
                ldsm4(kl4, kb_l + off);
                mma16816(s[2*g],   qfh[kc], kh4[0], kh4[1]);
                mma16816(s[2*g+1], qfh[kc], kh4[2], kh4[3]);
                mma16816(s[2*g],   qfh[kc], kl4[0], kl4[1]);
                mma16816(s[2*g+1], qfh[kc], kl4[2], kl4[3]);
                mma16816(s[2*g],   qfl[kc], kh4[0], kh4[1]);
                mma16816(s[2*g+1], qfl[kc], kh4[2], kh4[3]);
            }
        }

        // ---- mask tail keys ----
        if (n0 + 64 > NPIX) {
            int c2 = 2*(ln & 3);
#pragma unroll
            for (int j = 0; j < 8; j++) {
                int col = n0 + 8*j + c2;
                if (col >= NPIX) { s[j][0] = s[j][1] = s[j][2] = s[j][3] = -1e30f; }
            }
        }

        // ---- online softmax ----
        float bm0 = -1e30f, bm1 = -1e30f;
#pragma unroll
        for (int j = 0; j < 8; j++) {
            bm0 = fmaxf(bm0, fmaxf(s[j][0], s[j][1]));
            bm1 = fmaxf(bm1, fmaxf(s[j][2], s[j][3]));
        }
        bm0 = fmaxf(bm0, __shfl_xor_sync(0xffffffffu, bm0, 1));
        bm0 = fmaxf(bm0, __shfl_xor_sync(0xffffffffu, bm0, 2));
        bm1 = fmaxf(bm1, __shfl_xor_sync(0xffffffffu, bm1, 1));
        bm1 = fmaxf(bm1, __shfl_xor_sync(0xffffffffu, bm1, 2));
        float nm0 = fmaxf(rm0, bm0), nm1 = fmaxf(rm1, bm1);
        float sc0 = __expf(rm0 - nm0), sc1 = __expf(rm1 - nm1);
        rm0 = nm0; rm1 = nm1;
        float bs0 = 0.f, bs1 = 0.f;
#pragma unroll
        for (int j = 0; j < 8; j++) {
            s[j][0] = __expf(s[j][0] - nm0);
            s[j][1] = __expf(s[j][1] - nm0);
            s[j][2] = __expf(s[j][2] - nm1);
            s[j][3] = __expf(s[j][3] - nm1);
            bs0 += s[j][0] + s[j][1];
            bs1 += s[j][2] + s[j][3];
        }
        bs0 += __shfl_xor_sync(0xffffffffu, bs0, 1);
        bs0 += __shfl_xor_sync(0xffffffffu, bs0, 2);
        bs1 += __shfl_xor_sync(0xffffffffu, bs1, 1);
        bs1 += __shfl_xor_sync(0xffffffffu, bs1, 2);
        rl0 = rl0*sc0 + bs0;
        rl1 = rl1*sc1 + bs1;
#pragma unroll
        for (int j = 0; j < 6; j++) {
            O[j][0] *= sc0; O[j][1] *= sc0;
            O[j][2] *= sc1; O[j][3] *= sc1;
        }

        // ---- O += P V (P fragments re-packed from S regs, split hi/lo) ----
#pragma unroll
        for (int kc = 0; kc < 4; kc++) {
            uint32_t ph[4], pl[4];
            {
                bf16 h0, l0_, h1, l1_;
                split_bf16(s[2*kc][0], h0, l0_); split_bf16(s[2*kc][1], h1, l1_);
                ph[0] = pack_bf2(h0, h1); pl[0] = pack_bf2(l0_, l1_);
                split_bf16(s[2*kc][2], h0, l0_); split_bf16(s[2*kc][3], h1, l1_);
                ph[1] = pack_bf2(h0, h1); pl[1] = pack_bf2(l0_, l1_);
                split_bf16(s[2*kc+1][0], h0, l0_); split_bf16(s[2*kc+1][1], h1, l1_);
                ph[2] = pack_bf2(h0, h1); pl[2] = pack_bf2(l0_, l1_);
                split_bf16(s[2*kc+1][2], h0, l0_); split_bf16(s[2*kc+1][3], h1, l1_);
                ph[3] = pack_bf2(h0, h1); pl[3] = pack_bf2(l0_, l1_);
            }
#pragma unroll
            for (int dg = 0; dg < 3; dg++) {
                uint32_t off = (uint32_t)(((dg*16 + brow)*AV_STR + kc*16 + bcol) * 2);
                uint32_t vh4[4], vl4[4];
                ldsm4(vh4, vb_h + off);
                ldsm4(vl4, vb_l + off);
                mma16816(O[2*dg],   ph, vh4[0], vh4[1]);
                mma16816(O[2*dg+1], ph, vh4[2], vh4[3]);
                mma16816(O[2*dg],   ph, vl4[0], vl4[1]);
                mma16816(O[2*dg+1], ph, vl4[2], vl4[3]);
                mma16816(O[2*dg],   pl, vh4[0], vh4[1]);
                mma16816(O[2*dg+1], pl, vh4[2], vh4[3]);
            }
        }
    }

    // ---- epilogue: normalize + split-store ----
    float inv0 = 1.f / rl0, inv1 = 1.f / rl1;
    int r0 = q0 + w*16 + (ln >> 2);
    int r1 = r0 + 8;
    int cbase = h*HDIM + 2*(ln & 3);
#pragma unroll
    for (int jn = 0; jn < 6; jn++) {
        int c = cbase + 8*jn;
        if (r0 < NPIX) {
            size_t idx = (size_t)(b*NPIX + r0)*C_DIM + c;
            bf16 h0, l0_, h1, l1_;
            split_bf16(O[jn][0]*inv0, h0, l0_);
            split_bf16(O[jn][1]*inv0, h1, l1_);
            *(uint32_t*)&AOh[idx] = pack_bf2(h0, h1);
            *(uint32_t*)&AOl[idx] = pack_bf2(l0_, l1_);
        }
        if (r1 < NPIX) {
            size_t idx = (size_t)(b*NPIX + r1)*C_DIM + c;
            bf16 h0, l0_, h1, l1_;
            split_bf16(O[jn][2]*inv1, h0, l0_);
            split_bf16(O[jn][3]*inv1, h1, l1_);
            *(uint32_t*)&AOh[idx] = pack_bf2(h0, h1);
            *(uint32_t*)&AOl[idx] = pack_bf2(l0_, l1_);
        }
    }
}

// ---------------- host ----------------
extern "C" void kernel_launch(void* const* d_in, const int* in_sizes, int n_in,
                              void* d_out, int out_size)
{
    const float* x       = (const float*)d_in[0];
    const float* local_w = (const float*)d_in[1];
    const float* local_b = (const float*)d_in[2];
    const float* bn1_g   = (const float*)d_in[3];
    const float* bn1_b   = (const float*)d_in[4];
    const float* bn1_m   = (const float*)d_in[5];
    const float* bn1_v   = (const float*)d_in[6];
    const float* q_w     = (const float*)d_in[7];
    const float* q_b     = (const float*)d_in[8];
    const float* k_w     = (const float*)d_in[9];
    const float* k_b     = (const float*)d_in[10];
    const float* v_w     = (const float*)d_in[11];
    const float* v_b     = (const float*)d_in[12];
    const float* proj_w  = (const float*)d_in[13];
    const float* proj_b  = (const float*)d_in[14];
    const float* ffn1_w  = (const float*)d_in[15];
    const float* ffn1_b  = (const float*)d_in[16];
    const float* ffn2_w  = (const float*)d_in[17];
    const float* ffn2_b  = (const float*)d_in[18];
    const float* bn2_g   = (const float*)d_in[19];
    const float* bn2_b   = (const float*)d_in[20];
    const float* bn2_m   = (const float*)d_in[21];
    const float* bn2_v   = (const float*)d_in[22];

    float *lx, *r;
    bf16 *lxh, *lxl, *qh, *ql, *kh, *kl, *vth, *vtl, *aoh, *aol, *hh, *hl, *f1h, *f1l;
    bf16 *qwh, *qwl, *kwh, *kwl, *vwh, *vwl, *pwh, *pwl, *w1h, *w1l, *w2h, *w2l;
    cudaGetSymbolAddress((void**)&lx,  g_lx);
    cudaGetSymbolAddress((void**)&lxh, g_lxh);
    cudaGetSymbolAddress((void**)&lxl, g_lxl);
    cudaGetSymbolAddress((void**)&qh,  g_qh);
    cudaGetSymbolAddress((void**)&ql,  g_ql);
    cudaGetSymbolAddress((void**)&kh,  g_kh);
    cudaGetSymbolAddress((void**)&kl,  g_kl);
    cudaGetSymbolAddress((void**)&vth, g_vth);
    cudaGetSymbolAddress((void**)&vtl, g_vtl);
    cudaGetSymbolAddress((void**)&aoh, g_aoh);
    cudaGetSymbolAddress((void**)&aol, g_aol);
    cudaGetSymbolAddress((void**)&r,   g_r);
    cudaGetSymbolAddress((void**)&hh,  g_hh);
    cudaGetSymbolAddress((void**)&hl,  g_hl);
    cudaGetSymbolAddress((void**)&f1h, g_f1h);
    cudaGetSymbolAddress((void**)&f1l, g_f1l);
    cudaGetSymbolAddress((void**)&qwh, g_qwh); cudaGetSymbolAddress((void**)&qwl, g_qwl);
    cudaGetSymbolAddress((void**)&kwh, g_kwh); cudaGetSymbolAddress((void**)&kwl, g_kwl);
    cudaGetSymbolAddress((void**)&vwh, g_vwh); cudaGetSymbolAddress((void**)&vwl, g_vwl);
    cudaGetSymbolAddress((void**)&pwh, g_pwh); cudaGetSymbolAddress((void**)&pwl, g_pwl);
    cudaGetSymbolAddress((void**)&w1h, g_w1h); cudaGetSymbolAddress((void**)&w1l, g_w1l);
    cudaGetSymbolAddress((void**)&w2h, g_w2h); cudaGetSymbolAddress((void**)&w2l, g_w2l);

    cudaFuncSetAttribute(gemm_mma<0>, cudaFuncAttributeMaxDynamicSharedMemorySize, GEMM_SMEM);
    cudaFuncSetAttribute(gemm_mma<1>, cudaFuncAttributeMaxDynamicSharedMemorySize, GEMM_SMEM);
    cudaFuncSetAttribute(gemm_mma<2>, cudaFuncAttributeMaxDynamicSharedMemorySize, GEMM_SMEM);
    cudaFuncSetAttribute(gemm_mma<3>, cudaFuncAttributeMaxDynamicSharedMemorySize, GEMM_SMEM);
    cudaFuncSetAttribute(gemm_mma<4>, cudaFuncAttributeMaxDynamicSharedMemorySize, GEMM_SMEM);
    cudaFuncSetAttribute(attn_mma,    cudaFuncAttributeMaxDynamicSharedMemorySize, ATTN_SMEM);

    // 0. all weight conversions in one launch
    cvt_all_kernel<<<(4*NW + 2*NF + 255)/256, 256>>>(
        q_w, qwh, qwl, k_w, kwh, kwl, v_w, vwh, vwl,
        proj_w, pwh, pwl, ffn1_w, w1h, w1l, ffn2_w, w2h, w2l);

    // 1. fused depthwise conv + BN1 + transpose -> token-major (+ bf16 split)
    conv_tokens_kernel<<<dim3(25, 12, BATCH), dim3(32, 8)>>>(
        x, local_w, local_b, bn1_g, bn1_b, bn1_m, bn1_v);

    dim3 g384(3, 49), g1536(12, 49);
    const float scale = 0.14433756729740643f;   // 48^-0.5

    // 2. QKV: Q (scale folded) / K -> [t][c] hi/lo; V -> [b][h][d][n] hi/lo
    gemm_mma<0><<<g384, 256, GEMM_SMEM>>>(lxh, lxl, qwh, qwl, q_b, nullptr,
        nullptr, nullptr, nullptr, nullptr, nullptr, qh, ql, C_DIM, C_DIM, scale);
    gemm_mma<0><<<g384, 256, GEMM_SMEM>>>(lxh, lxl, kwh, kwl, k_b, nullptr,
        nullptr, nullptr, nullptr, nullptr, nullptr, kh, kl, C_DIM, C_DIM, 1.0f);
    gemm_mma<4><<<g384, 256, GEMM_SMEM>>>(lxh, lxl, vwh, vwl, v_b, nullptr,
        nullptr, nullptr, nullptr, nullptr, nullptr, vth, vtl, C_DIM, C_DIM, 1.0f);

    // 3. flash attention (tensor cores, pipelined K/V) -> ao hi/lo
    attn_mma<<<dim3(7, HEADS, BATCH), 256, ATTN_SMEM>>>(qh, ql, kh, kl, vth, vtl, aoh, aol);

    // 4. proj + residual(lx) -> r (f32); BN2 -> h (hi/lo)
    gemm_mma<1><<<g384, 256, GEMM_SMEM>>>(aoh, aol, pwh, pwl, proj_b, lx,
        bn2_g, bn2_b, bn2_m, bn2_v, r, hh, hl, C_DIM, C_DIM, 1.0f);

    // 5. FFN1 + gelu -> f1 (hi/lo)
    gemm_mma<2><<<g1536, 256, GEMM_SMEM>>>(hh, hl, w1h, w1l, ffn1_b, nullptr,
        nullptr, nullptr, nullptr, nullptr, nullptr, f1h, f1l, C_DIM, FFN_DIM, 1.0f);

    // 6. FFN2 + residual(r), NCHW output
    gemm_mma<3><<<g384, 256, GEMM_SMEM>>>(f1h, f1l, w2h, w2l, ffn2_b, r,
        nullptr, nullptr, nullptr, nullptr, (float*)d_out, nullptr, nullptr, FFN_DIM, C_DIM, 1.0f);
}

// round 12
// speedup vs baseline: 1.0055x; 1.0055x over previous
#include <cuda_runtime.h>
#include <cuda_bf16.h>
#include <math.h>
#include <stdint.h>

typedef __nv_bfloat16 bf16;

#define BATCH   16
#define C_DIM   384
#define NPIX    784
#define T_TOK   (BATCH*NPIX)      // 12544
#define HEADS   8
#define HDIM    48
#define FFN_DIM 1536
#define BN_EPS  1e-5f

// ---------------- scratch (static device globals; no allocation) ----------------
__device__ float g_lx [T_TOK*C_DIM];        // token-major f32 (residual for proj)
__device__ bf16  g_lxh[T_TOK*C_DIM];
__device__ bf16  g_lxl[T_TOK*C_DIM];
__device__ bf16  g_qh [T_TOK*C_DIM];        // Q (scale folded) hi/lo, [t][c]
__device__ bf16  g_ql [T_TOK*C_DIM];
__device__ bf16  g_kh [T_TOK*C_DIM];        // K hi/lo, [t][c]
__device__ bf16  g_kl [T_TOK*C_DIM];
__device__ bf16  g_vth[T_TOK*C_DIM + 64];   // V^T hi/lo, [b][h][d][n] (+pad for tail overread)
__device__ bf16  g_vtl[T_TOK*C_DIM + 64];
__device__ bf16  g_aoh[T_TOK*C_DIM];        // attention out hi/lo
__device__ bf16  g_aol[T_TOK*C_DIM];
__device__ float g_r  [T_TOK*C_DIM];        // residual (proj + lx), f32
__device__ bf16  g_hh [T_TOK*C_DIM];        // bn2(residual) hi/lo
__device__ bf16  g_hl [T_TOK*C_DIM];
__device__ bf16  g_f1h[T_TOK*FFN_DIM];      // ffn1 output hi/lo
__device__ bf16  g_f1l[T_TOK*FFN_DIM];
// weights hi/lo
__device__ bf16  g_qwh[C_DIM*C_DIM], g_qwl[C_DIM*C_DIM];
__device__ bf16  g_kwh[C_DIM*C_DIM], g_kwl[C_DIM*C_DIM];
__device__ bf16  g_vwh[C_DIM*C_DIM], g_vwl[C_DIM*C_DIM];
__device__ bf16  g_pwh[C_DIM*C_DIM], g_pwl[C_DIM*C_DIM];
__device__ bf16  g_w1h[FFN_DIM*C_DIM], g_w1l[FFN_DIM*C_DIM];
__device__ bf16  g_w2h[C_DIM*FFN_DIM], g_w2l[C_DIM*FFN_DIM];

// ======================= helpers =======================
__device__ __forceinline__ uint32_t smem_u32(const void* p) {
    return (uint32_t)__cvta_generic_to_shared(p);
}
__device__ __forceinline__ void split_bf16(float x, bf16& hi, bf16& lo) {
    hi = __float2bfloat16_rn(x);
    lo = __float2bfloat16_rn(x - __bfloat162float(hi));
}
__device__ __forceinline__ uint32_t pack_bf2(bf16 a, bf16 b) {
    __nv_bfloat162 t; t.x = a; t.y = b;
    return *reinterpret_cast<uint32_t*>(&t);
}
__device__ __forceinline__ void ldsm4(uint32_t* r, uint32_t addr) {
    asm volatile("ldmatrix.sync.aligned.m8n8.x4.shared.b16 {%0,%1,%2,%3}, [%4];"
                 : "=r"(r[0]), "=r"(r[1]), "=r"(r[2]), "=r"(r[3]) : "r"(addr));
}
__device__ __forceinline__ void mma16816(float* c, const uint32_t* a, uint32_t b0, uint32_t b1) {
    asm volatile("mma.sync.aligned.m16n8k16.row.col.f32.bf16.bf16.f32 "
                 "{%0,%1,%2,%3}, {%4,%5,%6,%7}, {%8,%9}, {%0,%1,%2,%3};"
                 : "+f"(c[0]), "+f"(c[1]), "+f"(c[2]), "+f"(c[3])
                 : "r"(a[0]), "r"(a[1]), "r"(a[2]), "r"(a[3]), "r"(b0), "r"(b1));
}
__device__ __forceinline__ void cp16(uint32_t dst, const void* src) {
    asm volatile("cp.async.cg.shared.global [%0], [%1], 16;" :: "r"(dst), "l"(src));
}
#define CP_COMMIT() asm volatile("cp.async.commit_group;")
#define CP_WAIT1()  asm volatile("cp.async.wait_group 1;")
#define CP_WAIT0()  asm volatile("cp.async.wait_group 0;")

// ---------------- merged f32 -> bf16 hi/lo conversion (all weights) ----------------
#define NW (C_DIM*C_DIM)       // 147456
#define NF (FFN_DIM*C_DIM)     // 589824
__global__ void cvt_all_kernel(
    const float* __restrict__ s0, bf16* __restrict__ h0, bf16* __restrict__ l0,
    const float* __restrict__ s1, bf16* __restrict__ h1, bf16* __restrict__ l1,
    const float* __restrict__ s2, bf16* __restrict__ h2, bf16* __restrict__ l2,
    const float* __restrict__ s3, bf16* __restrict__ h3, bf16* __restrict__ l3,
    const float* __restrict__ s4, bf16* __restrict__ h4, bf16* __restrict__ l4,
    const float* __restrict__ s5, bf16* __restrict__ h5, bf16* __restrict__ l5)
{
    int idx = blockIdx.x * 256 + threadIdx.x;
    const float* s; bf16 *h, *l; int off;
    if (idx < 4*NW) {
        int w = idx / NW; off = idx - w*NW;
        s = (w==0) ? s0 : (w==1) ? s1 : (w==2) ? s2 : s3;
        h = (w==0) ? h0 : (w==1) ? h1 : (w==2) ? h2 : h3;
        l = (w==0) ? l0 : (w==1) ? l1 : (w==2) ? l2 : l3;
    } else {
        int i2 = idx - 4*NW;
        if (i2 < NF)            { s = s4; h = h4; l = l4; off = i2; }
        else if (i2 < 2*NF)     { s = s5; h = h5; l = l5; off = i2 - NF; }
        else return;
    }
    bf16 hi, lo; split_bf16(s[off], hi, lo); h[off] = hi; l[off] = lo;
}

// ---------------- fused depthwise 3x3 conv + BN1 + transpose -> token-major ----------------
__global__ void conv_tokens_kernel(const float* __restrict__ x,
                                   const float* __restrict__ w,
                                   const float* __restrict__ bconv,
                                   const float* __restrict__ bg,
                                   const float* __restrict__ bb,
                                   const float* __restrict__ bm,
                                   const float* __restrict__ bv)
{
    __shared__ float tile[32][33];
    int b   = blockIdx.z;
    int hw0 = blockIdx.x * 32;
    int c0  = blockIdx.y * 32;
    int tx = threadIdx.x, ty = threadIdx.y;   // 32 x 8
#pragma unroll
    for (int j = 0; j < 32; j += 8) {
        int c = c0 + ty + j, hw = hw0 + tx;
        float val = 0.f;
        if (hw < NPIX) {
            int yy = hw / 28, xx = hw % 28;
            const float* xp = x + ((size_t)b*C_DIM + c) * NPIX;
            const float* wp = w + c * 9;
            float s = 0.f;
#pragma unroll
            for (int ky = 0; ky < 3; ky++) {
                int y = yy + ky - 1;
                if ((unsigned)y < 28u) {
#pragma unroll
                    for (int kx = 0; kx < 3; kx++) {
                        int x2 = xx + kx - 1;
                        if ((unsigned)x2 < 28u) s += wp[ky*3+kx] * xp[y*28 + x2];
                    }
                }
            }
            s += bconv[c];
            float inv = rsqrtf(bv[c] + BN_EPS);
            val = (s - bm[c]) * inv * bg[c] + bb[c];
        }
        tile[ty + j][tx] = val;
    }
    __syncthreads();
#pragma unroll
    for (int j = 0; j < 32; j += 8) {
        int hw = hw0 + ty + j, c = c0 + tx;
        if (hw < NPIX) {
            float v = tile[tx][ty + j];
            size_t idx = ((size_t)b*NPIX + hw)*C_DIM + c;
            g_lx[idx] = v;
            bf16 hi, lo; split_bf16(v, hi, lo);
            g_lxh[idx] = hi; g_lxl[idx] = lo;
        }
    }
}

// ======================= cp.async double-buffered split-bf16 GEMM =======================
// CTA tile 256x128, 8 warps 4(m)x2(n), warp tile 64x64, K chunk 32, 2 stages.
// Per K=16 step: load ALL fragments (16 ldsm4), then issue 96 MMAs in 3 passes
// by product type (hh, hl, lh) -> same-accumulator reuse distance 32 (was 2).
#define TM    256
#define TN    128
#define KC    32
#define ASTR  40
#define A_TILE_ELE (TM*ASTR)                 // 10240
#define W_TILE_ELE (TN*ASTR)                 // 5120
#define A_TILE_B (A_TILE_ELE*2)              // 20480 B
#define W_TILE_B (W_TILE_ELE*2)              // 10240 B
#define STAGE_B  (2*A_TILE_B + 2*W_TILE_B)   // 61440 B
#define GEMM_SMEM (2*STAGE_B)                // 122880 B

__device__ __forceinline__ void gemm_load_stage(
    const bf16* __restrict__ Ah, const bf16* __restrict__ Al,
    const bf16* __restrict__ Wh, const bf16* __restrict__ Wl,
    int t0, int o0, int K, int k0, uint32_t su)
{
    int tid = threadIdx.x;
#pragma unroll
    for (int i = 0; i < 4; ++i) {            // A: 256 rows x 4 chunks per type
        int ch = tid + i*256;
        int r = ch >> 2, c = ch & 3;
        uint32_t d = (uint32_t)((r*ASTR + c*8) * 2);
        size_t so = (size_t)(t0 + r)*K + k0 + c*8;
        cp16(su + d,            Ah + so);
        cp16(su + A_TILE_B + d, Al + so);
    }
#pragma unroll
    for (int i = 0; i < 2; ++i) {            // W: 128 rows x 4 chunks per type
        int ch = tid + i*256;
        int r = ch >> 2, c = ch & 3;
        uint32_t d = (uint32_t)((r*ASTR + c*8) * 2);
        size_t so = (size_t)(o0 + r)*K + k0 + c*8;
        cp16(su + 2*A_TILE_B + d,            Wh + so);
        cp16(su + 2*A_TILE_B + W_TILE_B + d, Wl + so);
    }
    CP_COMMIT();
}

template<int MODE>
__global__ void __launch_bounds__(256, 1)
gemm_mma(const bf16* __restrict__ Ah, const bf16* __restrict__ Al,
         const bf16* __restrict__ Wh, const bf16* __restrict__ Wl,
         const float* __restrict__ bias, const float* __restrict__ res,
         const float* __restrict__ bng, const float* __restrict__ bnb,
         const float* __restrict__ bnm, const float* __restrict__ bnv,
         float* __restrict__ outf, bf16* __restrict__ oh, bf16* __restrict__ ol,
         int K, int N, float mult)
{
    extern __shared__ __align__(16) bf16 smb[];
    const uint32_t s0u = smem_u32(smb);

    const int tid = threadIdx.x;
    const int wid = tid >> 5, l = tid & 31;
    const int wm = wid & 3, wn = wid >> 2;    // warp tile: rows wm*64, cols wn*64
    const int t0 = blockIdx.y * TM;
    const int o0 = blockIdx.x * TN;

    float acc[4][8][4];
#pragma unroll
    for (int f = 0; f < 4; f++)
#pragma unroll
        for (int g = 0; g < 8; g++)
#pragma unroll
            for (int i = 0; i < 4; i++) acc[f][g][i] = 0.f;

    const int arow = l & 15;
    const int acol = (l >> 4) * 8;
    const int brow = ((l >> 4) << 3) + (l & 7);
    const int bcol = ((l >> 3) & 1) * 8;

    const int nch = K / KC;
    gemm_load_stage(Ah, Al, Wh, Wl, t0, o0, K, 0, s0u);

    for (int ch = 0; ch < nch; ++ch) {
        const int buf = ch & 1;
        __syncthreads();                               // stage buf^1 fully consumed
        if (ch + 1 < nch) {
            gemm_load_stage(Ah, Al, Wh, Wl, t0, o0, K, (ch+1)*KC,
                            s0u + (uint32_t)(buf ^ 1) * STAGE_B);
            CP_WAIT1();
        } else {
            CP_WAIT0();
        }
        __syncthreads();                               // stage buf visible to all

        const uint32_t sa = s0u + (uint32_t)buf * STAGE_B;
#pragma unroll
        for (int kk = 0; kk < 2; ++kk) {
            const int k0 = kk * 16;
            // ---- load ALL fragments for this K=16 step ----
            uint32_t ah[4][4], al2[4][4], bh[4][4], bl[4][4];
#pragma unroll
            for (int f = 0; f < 4; ++f) {
                uint32_t off = (uint32_t)(((wm*64 + f*16 + arow)*ASTR + k0 + acol) * 2);
                ldsm4(ah[f],  sa + off);
                ldsm4(al2[f], sa + A_TILE_B + off);
            }
#pragma unroll
            for (int gp = 0; gp < 4; ++gp) {
                uint32_t off = (uint32_t)(((wn*64 + gp*16 + brow)*ASTR + k0 + bcol) * 2);
                ldsm4(bh[gp], sa + 2*A_TILE_B + off);
                ldsm4(bl[gp], sa + 2*A_TILE_B + W_TILE_B + off);
            }
            // ---- pass 1: hi*hi (32 independent MMAs) ----
#pragma unroll
            for (int f = 0; f < 4; ++f)
#pragma unroll
                for (int gp = 0; gp < 4; ++gp) {
                    mma16816(acc[f][2*gp],   ah[f], bh[gp][0], bh[gp][1]);
                    mma16816(acc[f][2*gp+1], ah[f], bh[gp][2], bh[gp][3]);
                }
            // ---- pass 2: hi*lo ----
#pragma unroll
            for (int f = 0; f < 4; ++f)
#pragma unroll
                for (int gp = 0; gp < 4; ++gp) {
                    mma16816(acc[f][2*gp],   ah[f], bl[gp][0], bl[gp][1]);
                    mma16816(acc[f][2*gp+1], ah[f], bl[gp][2], bl[gp][3]);
                }
            // ---- pass 3: lo*hi ----
#pragma unroll
            for (int f = 0; f < 4; ++f)
#pragma unroll
                for (int gp = 0; gp < 4; ++gp) {
                    mma16816(acc[f][2*gp],   al2[f], bh[gp][0], bh[gp][1]);
                    mma16816(acc[f][2*gp+1], al2[f], bh[gp][2], bh[gp][3]);
                }
        }
    }

    // ---- epilogue ----
    const int row_in = l >> 2, col_in = (l & 3) * 2;
#pragma unroll
    for (int f = 0; f < 4; ++f) {
        const int tb = t0 + wm*64 + f*16 + row_in;
#pragma unroll
        for (int g = 0; g < 8; ++g) {
            const int o = o0 + wn*64 + g*8 + col_in;
#pragma unroll
            for (int hhalf = 0; hhalf < 2; ++hhalf) {
                const int t = tb + hhalf*8;
                const float c0 = acc[f][g][hhalf*2 + 0];
                const float c1 = acc[f][g][hhalf*2 + 1];
                if (MODE == 0) {
                    float v0 = (c0 + bias[o]) * mult;
                    float v1 = (c1 + bias[o+1]) * mult;
                    bf16 h0, l0_, h1, l1_;
                    split_bf16(v0, h0, l0_); split_bf16(v1, h1, l1_);
                    *(uint32_t*)&oh[(size_t)t*N + o] = pack_bf2(h0, h1);
                    *(uint32_t*)&ol[(size_t)t*N + o] = pack_bf2(l0_, l1_);
                } else if (MODE == 1) {
#pragma unroll
                    for (int u = 0; u < 2; ++u) {
                        int oo = o + u;
                        size_t idx = (size_t)t*C_DIM + oo;
                        float val = (u ? c1 : c0) + bias[oo] + res[idx];
                        outf[idx] = val;
                        float inv = rsqrtf(bnv[oo] + BN_EPS);
                        float hb = (val - bnm[oo]) * inv * bng[oo] + bnb[oo];
                        bf16 hi, lo; split_bf16(hb, hi, lo);
                        oh[idx] = hi; ol[idx] = lo;
                    }
                } else if (MODE == 2) {
#pragma unroll
                    for (int u = 0; u < 2; ++u) {
                        int oo = o + u;
                        float val = (u ? c1 : c0) + bias[oo];
                        float ge = 0.5f * val * (1.0f + erff(val * 0.7071067811865475f));
                        size_t idx = (size_t)t*N + oo;
                        bf16 hi, lo; split_bf16(ge, hi, lo);
                        oh[idx] = hi; ol[idx] = lo;
                    }
                } else if (MODE == 3) { // NCHW final
                    const int bb2 = t / NPIX;
                    const int nn  = t - bb2 * NPIX;
#pragma unroll
                    for (int u = 0; u < 2; ++u) {
                        int oo = o + u;
                        float val = (u ? c1 : c0) + bias[oo] + res[(size_t)t*C_DIM + oo];
                        outf[((size_t)bb2*C_DIM + oo)*NPIX + nn] = val;
                    }
                } else { // MODE 4: V head-transposed [b][h][d][n]
                    const int bb2 = t / NPIX;
                    const int nn  = t - bb2 * NPIX;
#pragma unroll
                    for (int u = 0; u < 2; ++u) {
                        int oo = o + u;
                        int hh2 = oo / HDIM, dd = oo - hh2*HDIM;
                        float val = (u ? c1 : c0) + bias[oo];
                        bf16 hi, lo; split_bf16(val, hi, lo);
                        size_t dst = ((size_t)((bb2*HEADS + hh2)*HDIM + dd))*NPIX + nn;
                        oh[dst] = hi; ol[dst] = lo;
                    }
                }
            }
        }
    }
}

// ======================= flash-style mma attention (cp.async K/V pipeline) =======================
#define AQ_STR 56
#define AK_STR 56
#define AV_STR 72
#define K_STAGE_ELE (64*AK_STR)   // 3584
#define V_STAGE_ELE (48*AV_STR)   // 3456
#define ATTN_SMEM ((2*128*AQ_STR + 4*K_STAGE_ELE + 4*V_STAGE_ELE) * 2)   // 84992 B
#define NBLK ((NPIX + 63) / 64)   // 13

__device__ __forceinline__ void attn_load_kv(
    const bf16* __restrict__ Kh, const bf16* __restrict__ Kl,
    const bf16* __restrict__ Vth, const bf16* __restrict__ Vtl,
    int b, int h, int n0,
    uint32_t kh_u, uint32_t kl_u, uint32_t vh_u, uint32_t vl_u)
{
    int tid = threadIdx.x;
    for (int idx = tid; idx < 64*6; idx += 256) {
        int r = idx / 6, cs = idx % 6;
        int t = b*NPIX + min(n0 + r, NPIX - 1);
        size_t so = (size_t)t*C_DIM + h*HDIM + cs*8;
        uint32_t d = (uint32_t)((r*AK_STR + cs*8) * 2);
        cp16(kh_u + d, Kh + so);
        cp16(kl_u + d, Kl + so);
    }
    for (int idx = tid; idx < 48*8; idx += 256) {
        int r = idx / 8, cs = idx % 8;
        size_t so = ((size_t)((b*HEADS + h)*HDIM + r))*NPIX + n0 + cs*8;
        uint32_t d = (uint32_t)((r*AV_STR + cs*8) * 2);
        cp16(vh_u + d, Vth + so);
        cp16(vl_u + d, Vtl + so);
    }
    CP_COMMIT();
}

__global__ void __launch_bounds__(256)
attn_mma(const bf16* __restrict__ Qh, const bf16* __restrict__ Ql,
         const bf16* __restrict__ Kh, const bf16* __restrict__ Kl,
         const bf16* __restrict__ Vth, const bf16* __restrict__ Vtl,
         bf16* __restrict__ AOh, bf16* __restrict__ AOl)
{
    extern __shared__ __align__(16) bf16 sm_[];
    bf16* sQh = sm_;
    bf16* sQl = sQh + 128*AQ_STR;
    bf16* sK  = sQl + 128*AQ_STR;      // [stage][h/l]
    bf16* sV  = sK + 4*K_STAGE_ELE;

    const int tid = threadIdx.x, w = tid >> 5, ln = tid & 31;
    const int qb = blockIdx.x, h = blockIdx.y, b = blockIdx.z;
    const int q0 = qb * 128;

    uint32_t kstage_u[2][2], vstage_u[2][2];
#pragma unroll
    for (int s = 0; s < 2; s++) {
        kstage_u[s][0] = smem_u32(sK + s*2*K_STAGE_ELE);
        kstage_u[s][1] = kstage_u[s][0] + K_STAGE_ELE*2;
        vstage_u[s][0] = smem_u32(sV + s*2*V_STAGE_ELE);
        vstage_u[s][1] = vstage_u[s][0] + V_STAGE_ELE*2;
    }

    // prefetch K/V block 0 while Q loads
    attn_load_kv(Kh, Kl, Vth, Vtl, b, h, 0, kstage_u[0][0], kstage_u[0][1],
                 vstage_u[0][0], vstage_u[0][1]);

    // ---- load Q tile (rows clamped to image) ----
    for (int idx = tid; idx < 128*6; idx += 256) {
        int r = idx / 6, cs = idx % 6;
        int t = b*NPIX + min(q0 + r, NPIX - 1);
        const bf16* ph_ = Qh + (size_t)t*C_DIM + h*HDIM;
        const bf16* pl_ = Ql + (size_t)t*C_DIM + h*HDIM;
        *(uint4*)(sQh + r*AQ_STR + cs*8) = *((const uint4*)ph_ + cs);
        *(uint4*)(sQl + r*AQ_STR + cs*8) = *((const uint4*)pl_ + cs);
    }
    __syncthreads();

    // ---- Q fragments (persistent) ----
    const int arow = ln & 15, acol = (ln >> 4) * 8;
    const int brow = ((ln >> 4) << 3) + (ln & 7), bcol = ((ln >> 3) & 1) * 8;
    uint32_t qfh[3][4], qfl[3][4];
    {
        const uint32_t qb_h = smem_u32(sQh), qb_l = smem_u32(sQl);
#pragma unroll
        for (int kc = 0; kc < 3; kc++) {
            uint32_t off = (uint32_t)(((w*16 + arow)*AQ_STR + kc*16 + acol) * 2);
            ldsm4(qfh[kc], qb_h + off);
            ldsm4(qfl[kc], qb_l + off);
        }
    }

    float rm0 = -1e30f, rm1 = -1e30f;   // running max (rows ln/4, ln/4+8)
    float rl0 = 0.f,    rl1 = 0.f;      // running sum
    float O[6][4];
#pragma unroll
    for (int j = 0; j < 6; j++)
#pragma unroll
        for (int i = 0; i < 4; i++) O[j][i] = 0.f;

    for (int it = 0; it < NBLK; ++it) {
        const int buf = it & 1;
        const int n0 = it * 64;
        __syncthreads();                            // stage buf^1 fully consumed
        if (it + 1 < NBLK) {
            attn_load_kv(Kh, Kl, Vth, Vtl, b, h, (it+1)*64,
                         kstage_u[buf^1][0], kstage_u[buf^1][1],
                         vstage_u[buf^1][0], vstage_u[buf^1][1]);
            CP_WAIT1();
        } else {
            CP_WAIT0();
        }
        __syncthreads();

        const uint32_t kb_h = kstage_u[buf][0], kb_l = kstage_u[buf][1];
        const uint32_t vb_h = vstage_u[buf][0], vb_l = vstage_u[buf][1];

        // ---- S = Q K^T, MMAs grouped by product type per kc ----
        float s[8][4];
#pragma unroll
        for (int j = 0; j < 8; j++)
#pragma unroll
            for (int i = 0; i < 4; i++) s[j][i] = 0.f;

#pragma unroll
        for (int kc = 0; kc < 3; kc++) {
            uint32_t kh4[4][4], kl4[4][4];
#pragma unroll
            for (int g = 0; g < 4; g++) {
                uint32_t off = (uint32_t)(((g*16 + brow)*AK_STR + kc*16 + bcol) * 2);
                ldsm4(kh4[g], kb_h + off);
                ldsm4(kl4[g], kb_l + off);
            }
#pragma unroll
            for (int g = 0; g < 4; g++) {           // pass 1: qh*kh (8 independent)
                mma16816(s[2*g],   qfh[kc], kh4[g][0], kh4[g][1]);
                mma16816(s[2*g+1], qfh[kc], kh4[g][2], kh4[g][3]);
            }
#pragma unroll
            for (int g = 0; g < 4; g++) {           // pass 2: qh*kl
                mma16816(s[2*g],   qfh[kc], kl4[g][0], kl4[g][1]);
                mma16816(s[2*g+1], qfh[kc], kl4[g][2], kl4[g][3]);
            }
#pragma unroll
            for (int g = 0; g < 4; g++) {           // pass 3: ql*kh
                mma16816(s[2*g],   qfl[kc], kh4[g][0], kh4[g][1]);
                mma16816(s[2*g+1], qfl[kc], kh4[g][2], kh4[g][3]);
            }
        }

        // ---- mask tail keys ----
        if (n0 + 64 > NPIX) {
            int c2 = 2*(ln & 3);
#pragma unroll
            for (int j = 0; j < 8; j++) {
                int col = n0 + 8*j + c2;
                if (col >= NPIX) { s[j][0] = s[j][1] = s[j][2] = s[j][3] = -1e30f; }
            }
        }

        // ---- online softmax ----
        float bm0 = -1e30f, bm1 = -1e30f;
#pragma unroll
        for (int j = 0; j < 8; j++) {
            bm0 = fmaxf(bm0, fmaxf(s[j][0], s[j][1]));
            bm1 = fmaxf(bm1, fmaxf(s[j][2], s[j][3]));
        }
        bm0 = fmaxf(bm0, __shfl_xor_sync(0xffffffffu, bm0, 1));
        bm0 = fmaxf(bm0, __shfl_xor_sync(0xffffffffu, bm0, 2));
        bm1 = fmaxf(bm1, __shfl_xor_sync(0xffffffffu, bm1, 1));
        bm1 = fmaxf(bm1, __shfl_xor_sync(0xffffffffu, bm1, 2));
        float nm0 = fmaxf(rm0, bm0), nm1 = fmaxf(rm1, bm1);
        float sc0 = __expf(rm0 - nm0), sc1 = __expf(rm1 - nm1);
        rm0 = nm0; rm1 = nm1;
        float bs0 = 0.f, bs1 = 0.f;
#pragma unroll
        for (int j = 0; j < 8; j++) {
            s[j][0] = __expf(s[j][0] - nm0);
            s[j][1] = __expf(s[j][1] - nm0);
            s[j][2] = __expf(s[j][2] - nm1);
            s[j][3] = __expf(s[j][3] - nm1);
            bs0 += s[j][0] + s[j][1];
            bs1 += s[j][2] + s[j][3];
        }
        bs0 += __shfl_xor_sync(0xffffffffu, bs0, 1);
        bs0 += __shfl_xor_sync(0xffffffffu, bs0, 2);
        bs1 += __shfl_xor_sync(0xffffffffu, bs1, 1);
        bs1 += __shfl_xor_sync(0xffffffffu, bs1, 2);
        rl0 = rl0*sc0 + bs0;
        rl1 = rl1*sc1 + bs1;
#pragma unroll
        for (int j = 0; j < 6; j++) {
            O[j][0] *= sc0; O[j][1] *= sc0;
            O[j][2] *= sc1; O[j][3] *= sc1;
        }

        // ---- O += P V (P re-packed from S regs; MMAs grouped by product) ----
#pragma unroll
        for (int kc = 0; kc < 4; kc++) {
            uint32_t ph[4], pl[4];
            {
                bf16 h0, l0_, h1, l1_;
                split_bf16(s[2*kc][0], h0, l0_); split_bf16(s[2*kc][1], h1, l1_);
                ph[0] = pack_bf2(h0, h1); pl[0] = pack_bf2(l0_, l1_);
                split_bf16(s[2*kc][2], h0, l0_); split_bf16(s[2*kc][3], h1, l1_);
                ph[1] = pack_bf2(h0, h1); pl[1] = pack_bf2(l0_, l1_);
                split_bf16(s[2*kc+1][0], h0, l0_); split_bf16(s[2*kc+1][1], h1, l1_);
                ph[2] = pack_bf2(h0, h1); pl[2] = pack_bf2(l0_, l1_);
                split_bf16(s[2*kc+1][2], h0, l0_); split_bf16(s[2*kc+1][3], h1, l1_);
                ph[3] = pack_bf2(h0, h1); pl[3] = pack_bf2(l0_, l1_);
            }
            uint32_t vh4[3][4], vl4[3][4];
#pragma unroll
            for (int dg = 0; dg < 3; dg++) {
                uint32_t off = (uint32_t)(((dg*16 + brow)*AV_STR + kc*16 + bcol) * 2);
                ldsm4(vh4[dg], vb_h + off);
                ldsm4(vl4[dg], vb_l + off);
            }
#pragma unroll
            for (int dg = 0; dg < 3; dg++) {        // pass 1: ph*vh
                mma16816(O[2*dg],   ph, vh4[dg][0], vh4[dg][1]);
                mma16816(O[2*dg+1], ph, vh4[dg][2], vh4[dg][3]);
            }
#pragma unroll
            for (int dg = 0; dg < 3; dg++) {        // pass 2: ph*vl
                mma16816(O[2*dg],   ph, vl4[dg][0], vl4[dg][1]);
                mma16816(O[2*dg+1], ph, vl4[dg][2], vl4[dg][3]);
            }
#pragma unroll
            for (int dg = 0; dg < 3; dg++) {        // pass 3: pl*vh
                mma16816(O[2*dg],   pl, vh4[dg][0], vh4[dg][1]);
                mma16816(O[2*dg+1], pl, vh4[dg][2], vh4[dg][3]);
            }
        }
    }

    // ---- epilogue: normalize + split-store ----
    float inv0 = 1.f / rl0, inv1 = 1.f / rl1;
    int r0 = q0 + w*16 + (ln >> 2);
    int r1 = r0 + 8;
    int cbase = h*HDIM + 2*(ln & 3);
#pragma unroll
    for (int jn = 0; jn < 6; jn++) {
        int c = cbase + 8*jn;
        if (r0 < NPIX) {
            size_t idx = (size_t)(b*NPIX + r0)*C_DIM + c;
            bf16 h0, l0_, h1, l1_;
            split_bf16(O[jn][0]*inv0, h0, l0_);
            split_bf16(O[jn][1]*inv0, h1, l1_);
            *(uint32_t*)&AOh[idx] = pack_bf2(h0, h1);
            *(uint32_t*)&AOl[idx] = pack_bf2(l0_, l1_);
        }
        if (r1 < NPIX) {
            size_t idx = (size_t)(b*NPIX + r1)*C_DIM + c;
            bf16 h0, l0_, h1, l1_;
            split_bf16(O[jn][2]*inv1, h0, l0_);
            split_bf16(O[jn][3]*inv1, h1, l1_);
            *(uint32_t*)&AOh[idx] = pack_bf2(h0, h1);
            *(uint32_t*)&AOl[idx] = pack_bf2(l0_, l1_);
        }
    }
}

// ---------------- host ----------------
extern "C" void kernel_launch(void* const* d_in, const int* in_sizes, int n_in,
                              void* d_out, int out_size)
{
    const float* x       = (const float*)d_in[0];
    const float* local_w = (const float*)d_in[1];
    const float* local_b = (const float*)d_in[2];
    const float* bn1_g   = (const float*)d_in[3];
    const float* bn1_b   = (const float*)d_in[4];
    const float* bn1_m   = (const float*)d_in[5];
    const float* bn1_v   = (const float*)d_in[6];
    const float* q_w     = (const float*)d_in[7];
    const float* q_b     = (const float*)d_in[8];
    const float* k_w     = (const float*)d_in[9];
    const float* k_b     = (const float*)d_in[10];
    const float* v_w     = (const float*)d_in[11];
    const float* v_b     = (const float*)d_in[12];
    const float* proj_w  = (const float*)d_in[13];
    const float* proj_b  = (const float*)d_in[14];
    const float* ffn1_w  = (const float*)d_in[15];
    const float* ffn1_b  = (const float*)d_in[16];
    const float* ffn2_w  = (const float*)d_in[17];
    const float* ffn2_b  = (const float*)d_in[18];
    const float* bn2_g   = (const float*)d_in[19];
    const float* bn2_b   = (const float*)d_in[20];
    const float* bn2_m   = (const float*)d_in[21];
    const float* bn2_v   = (const float*)d_in[22];

    float *lx, *r;
    bf16 *lxh, *lxl, *qh, *ql, *kh, *kl, *vth, *vtl, *aoh, *aol, *hh, *hl, *f1h, *f1l;
    bf16 *qwh, *qwl, *kwh, *kwl, *vwh, *vwl, *pwh, *pwl, *w1h, *w1l, *w2h, *w2l;
    cudaGetSymbolAddress((void**)&lx,  g_lx);
    cudaGetSymbolAddress((void**)&lxh, g_lxh);
    cudaGetSymbolAddress((void**)&lxl, g_lxl);
    cudaGetSymbolAddress((void**)&qh,  g_qh);
    cudaGetSymbolAddress((void**)&ql,  g_ql);
    cudaGetSymbolAddress((void**)&kh,  g_kh);
    cudaGetSymbolAddress((void**)&kl,  g_kl);
    cudaGetSymbolAddress((void**)&vth, g_vth);
    cudaGetSymbolAddress((void**)&vtl, g_vtl);
    cudaGetSymbolAddress((void**)&aoh, g_aoh);
    cudaGetSymbolAddress((void**)&aol, g_aol);
    cudaGetSymbolAddress((void**)&r,   g_r);
    cudaGetSymbolAddress((void**)&hh,  g_hh);
    cudaGetSymbolAddress((void**)&hl,  g_hl);
    cudaGetSymbolAddress((void**)&f1h, g_f1h);
    cudaGetSymbolAddress((void**)&f1l, g_f1l);
    cudaGetSymbolAddress((void**)&qwh, g_qwh); cudaGetSymbolAddress((void**)&qwl, g_qwl);
    cudaGetSymbolAddress((void**)&kwh, g_kwh); cudaGetSymbolAddress((void**)&kwl, g_kwl);
    cudaGetSymbolAddress((void**)&vwh, g_vwh); cudaGetSymbolAddress((void**)&vwl, g_vwl);
    cudaGetSymbolAddress((void**)&pwh, g_pwh); cudaGetSymbolAddress((void**)&pwl, g_pwl);
    cudaGetSymbolAddress((void**)&w1h, g_w1h); cudaGetSymbolAddress((void**)&w1l, g_w1l);
    cudaGetSymbolAddress((void**)&w2h, g_w2h); cudaGetSymbolAddress((void**)&w2l, g_w2l);

    cudaFuncSetAttribute(gemm_mma<0>, cudaFuncAttributeMaxDynamicSharedMemorySize, GEMM_SMEM);
    cudaFuncSetAttribute(gemm_mma<1>, cudaFuncAttributeMaxDynamicSharedMemorySize, GEMM_SMEM);
    cudaFuncSetAttribute(gemm_mma<2>, cudaFuncAttributeMaxDynamicSharedMemorySize, GEMM_SMEM);
    cudaFuncSetAttribute(gemm_mma<3>, cudaFuncAttributeMaxDynamicSharedMemorySize, GEMM_SMEM);
    cudaFuncSetAttribute(gemm_mma<4>, cudaFuncAttributeMaxDynamicSharedMemorySize, GEMM_SMEM);
    cudaFuncSetAttribute(attn_mma,    cudaFuncAttributeMaxDynamicSharedMemorySize, ATTN_SMEM);

    // 0. all weight conversions in one launch
    cvt_all_kernel<<<(4*NW + 2*NF + 255)/256, 256>>>(
        q_w, qwh, qwl, k_w, kwh, kwl, v_w, vwh, vwl,
        proj_w, pwh, pwl, ffn1_w, w1h, w1l, ffn2_w, w2h, w2l);

    // 1. fused depthwise conv + BN1 + transpose -> token-major (+ bf16 split)
    conv_tokens_kernel<<<dim3(25, 12, BATCH), dim3(32, 8)>>>(
        x, local_w, local_b, bn1_g, bn1_b, bn1_m, bn1_v);

    dim3 g384(3, 49), g1536(12, 49);
    const float scale = 0.14433756729740643f;   // 48^-0.5

    // 2. QKV: Q (scale folded) / K -> [t][c] hi/lo; V -> [b][h][d][n] hi/lo
    gemm_mma<0><<<g384, 256, GEMM_SMEM>>>(lxh, lxl, qwh, qwl, q_b, nullptr,
        nullptr, nullptr, nullptr, nullptr, nullptr, qh, ql, C_DIM, C_DIM, scale);
    gemm_mma<0><<<g384, 256, GEMM_SMEM>>>(lxh, lxl, kwh, kwl, k_b, nullptr,
        nullptr, nullptr, nullptr, nullptr, nullptr, kh, kl, C_DIM, C_DIM, 1.0f);
    gemm_mma<4><<<g384, 256, GEMM_SMEM>>>(lxh, lxl, vwh, vwl, v_b, nullptr,
        nullptr, nullptr, nullptr, nullptr, nullptr, vth, vtl, C_DIM, C_DIM, 1.0f);

    // 3. flash attention (tensor cores, pipelined K/V) -> ao hi/lo
    attn_mma<<<dim3(7, HEADS, BATCH), 256, ATTN_SMEM>>>(qh, ql, kh, kl, vth, vtl, aoh, aol);

    // 4. proj + residual(lx) -> r (f32); BN2 -> h (hi/lo)
    gemm_mma<1><<<g384, 256, GEMM_SMEM>>>(aoh, aol, pwh, pwl, proj_b, lx,
        bn2_g, bn2_b, bn2_m, bn2_v, r, hh, hl, C_DIM, C_DIM, 1.0f);

    // 5. FFN1 + gelu -> f1 (hi/lo)
    gemm_mma<2><<<g1536, 256, GEMM_SMEM>>>(hh, hl, w1h, w1l, ffn1_b, nullptr,
        nullptr, nullptr, nullptr, nullptr, nullptr, f1h, f1l, C_DIM, FFN_DIM, 1.0f);

    // 6. FFN2 + residual(r), NCHW output
    gemm_mma<3><<<g384, 256, GEMM_SMEM>>>(f1h, f1l, w2h, w2l, ffn2_b, r,
        nullptr, nullptr, nullptr, nullptr, (float*)d_out, nullptr, nullptr, FFN_DIM, C_DIM, 1.0f);
}

// round 13
// speedup vs baseline: 2.1244x; 2.1128x over previous
#include <cuda_runtime.h>
#include <cuda_fp16.h>
#include <math.h>
#include <stdint.h>

typedef __half h16;

#define BATCH   16
#define C_DIM   384
#define NPIX    784
#define T_TOK   (BATCH*NPIX)      // 12544
#define HEADS   8
#define HDIM    48
#define FFN_DIM 1536
#define BN_EPS  1e-5f

// ---------------- scratch (static device globals; no allocation) ----------------
__device__ float g_lx [T_TOK*C_DIM];        // token-major f32 (residual for proj)
__device__ h16   g_lxf[T_TOK*C_DIM];
__device__ h16   g_qf [T_TOK*C_DIM];        // Q (scale folded), [t][c]
__device__ h16   g_kf [T_TOK*C_DIM];        // K, [t][c]
__device__ h16   g_vtf[T_TOK*C_DIM + 64];   // V^T, [b][h][d][n] (+pad for tail overread)
__device__ h16   g_aof[T_TOK*C_DIM];        // attention out
__device__ float g_r  [T_TOK*C_DIM];        // residual (proj + lx), f32
__device__ h16   g_hf [T_TOK*C_DIM];        // bn2(residual)
__device__ h16   g_f1f[T_TOK*FFN_DIM];      // ffn1 output
// weights fp16
__device__ h16   g_qw[C_DIM*C_DIM], g_kw[C_DIM*C_DIM], g_vw[C_DIM*C_DIM];
__device__ h16   g_pw[C_DIM*C_DIM];
__device__ h16   g_w1[FFN_DIM*C_DIM], g_w2[C_DIM*FFN_DIM];

// ======================= helpers =======================
__device__ __forceinline__ uint32_t smem_u32(const void* p) {
    return (uint32_t)__cvta_generic_to_shared(p);
}
__device__ __forceinline__ uint32_t pack_h2(h16 a, h16 b) {
    __half2 t = __halves2half2(a, b);
    return *reinterpret_cast<uint32_t*>(&t);
}
__device__ __forceinline__ void ldsm4(uint32_t* r, uint32_t addr) {
    asm volatile("ldmatrix.sync.aligned.m8n8.x4.shared.b16 {%0,%1,%2,%3}, [%4];"
                 : "=r"(r[0]), "=r"(r[1]), "=r"(r[2]), "=r"(r[3]) : "r"(addr));
}
__device__ __forceinline__ void mma16816(float* c, const uint32_t* a, uint32_t b0, uint32_t b1) {
    asm volatile("mma.sync.aligned.m16n8k16.row.col.f32.f16.f16.f32 "
                 "{%0,%1,%2,%3}, {%4,%5,%6,%7}, {%8,%9}, {%0,%1,%2,%3};"
                 : "+f"(c[0]), "+f"(c[1]), "+f"(c[2]), "+f"(c[3])
                 : "r"(a[0]), "r"(a[1]), "r"(a[2]), "r"(a[3]), "r"(b0), "r"(b1));
}
__device__ __forceinline__ void cp16(uint32_t dst, const void* src) {
    asm volatile("cp.async.cg.shared.global [%0], [%1], 16;" :: "r"(dst), "l"(src));
}
#define CP_COMMIT() asm volatile("cp.async.commit_group;")
#define CP_WAIT1()  asm volatile("cp.async.wait_group 1;")
#define CP_WAIT0()  asm volatile("cp.async.wait_group 0;")

// ---------------- merged f32 -> fp16 conversion (all weights) ----------------
#define NW (C_DIM*C_DIM)       // 147456
#define NF (FFN_DIM*C_DIM)     // 589824
__global__ void cvt_all_kernel(
    const float* __restrict__ s0, h16* __restrict__ h0,
    const float* __restrict__ s1, h16* __restrict__ h1,
    const float* __restrict__ s2, h16* __restrict__ h2,
    const float* __restrict__ s3, h16* __restrict__ h3,
    const float* __restrict__ s4, h16* __restrict__ h4,
    const float* __restrict__ s5, h16* __restrict__ h5)
{
    int idx = blockIdx.x * 256 + threadIdx.x;
    const float* s; h16* h; int off;
    if (idx < 4*NW) {
        int w = idx / NW; off = idx - w*NW;
        s = (w==0) ? s0 : (w==1) ? s1 : (w==2) ? s2 : s3;
        h = (w==0) ? h0 : (w==1) ? h1 : (w==2) ? h2 : h3;
    } else {
        int i2 = idx - 4*NW;
        if (i2 < NF)        { s = s4; h = h4; off = i2; }
        else if (i2 < 2*NF) { s = s5; h = h5; off = i2 - NF; }
        else return;
    }
    h[off] = __float2half_rn(s[off]);
}

// ---------------- fused depthwise 3x3 conv + BN1 + transpose -> token-major ----------------
__global__ void conv_tokens_kernel(const float* __restrict__ x,
                                   const float* __restrict__ w,
                                   const float* __restrict__ bconv,
                                   const float* __restrict__ bg,
                                   const float* __restrict__ bb,
                                   const float* __restrict__ bm,
                                   const float* __restrict__ bv)
{
    __shared__ float tile[32][33];
    int b   = blockIdx.z;
    int hw0 = blockIdx.x * 32;
    int c0  = blockIdx.y * 32;
    int tx = threadIdx.x, ty = threadIdx.y;   // 32 x 8
#pragma unroll
    for (int j = 0; j < 32; j += 8) {
        int c = c0 + ty + j, hw = hw0 + tx;
        float val = 0.f;
        if (hw < NPIX) {
            int yy = hw / 28, xx = hw % 28;
            const float* xp = x + ((size_t)b*C_DIM + c) * NPIX;
            const float* wp = w + c * 9;
            float s = 0.f;
#pragma unroll
            for (int ky = 0; ky < 3; ky++) {
                int y = yy + ky - 1;
                if ((unsigned)y < 28u) {
#pragma unroll
                    for (int kx = 0; kx < 3; kx++) {
                        int x2 = xx + kx - 1;
                        if ((unsigned)x2 < 28u) s += wp[ky*3+kx] * xp[y*28 + x2];
                    }
                }
            }
            s += bconv[c];
            float inv = rsqrtf(bv[c] + BN_EPS);
            val = (s - bm[c]) * inv * bg[c] + bb[c];
        }
        tile[ty + j][tx] = val;
    }
    __syncthreads();
#pragma unroll
    for (int j = 0; j < 32; j += 8) {
        int hw = hw0 + ty + j, c = c0 + tx;
        if (hw < NPIX) {
            float v = tile[tx][ty + j];
            size_t idx = ((size_t)b*NPIX + hw)*C_DIM + c;
            g_lx[idx]  = v;
            g_lxf[idx] = __float2half_rn(v);
        }
    }
}

// ======================= cp.async double-buffered fp16 GEMM =======================
// D[t][o] = sum_k A[t][k]*W[o][k], single fp16 product.
// CTA tile 128x128, 8 warps 4(m)x2(n), warp tile 32x64. K chunk 32, 2 stages.
#define KC    32
#define ASTR  40                             // fp16 row stride; conflict-free ldmatrix
#define TILE_ELE (128*ASTR)                  // 5120
#define TILE_B   (TILE_ELE*2)                // 10240 B
#define STAGE_B  (2*TILE_B)                  // 20480 B  (A + W)
#define GEMM_SMEM (2*STAGE_B)                // 40960 B

__device__ __forceinline__ void gemm_load_stage(
    const h16* __restrict__ A, const h16* __restrict__ W,
    int t0, int o0, int K, int k0, uint32_t su)
{
    int tid = threadIdx.x;
#pragma unroll
    for (int i = 0; i < 2; ++i) {
        int ch = tid + i*256;             // 0..511
        int r = ch >> 2, c = ch & 3;
        uint32_t d = (uint32_t)((r*ASTR + c*8) * 2);
        cp16(su + d,          A + (size_t)(t0 + r)*K + k0 + c*8);
        cp16(su + TILE_B + d, W + (size_t)(o0 + r)*K + k0 + c*8);
    }
    CP_COMMIT();
}

// MODE 0: (val+bias)*mult -> fp16 [t][N]        (Q with scale / K)
// MODE 1: +bias+res -> f32 out(r); BN2 -> fp16  (proj)
// MODE 2: gelu(+bias) -> fp16                   (ffn1)
// MODE 3: +bias+res -> NCHW f32                 (ffn2 final)
// MODE 4: +bias -> fp16, head-transposed [b][h][d][n]  (V)
template<int MODE>
__global__ void __launch_bounds__(256, 2)
gemm_mma(const h16* __restrict__ A, const h16* __restrict__ W,
         const float* __restrict__ bias, const float* __restrict__ res,
         const float* __restrict__ bng, const float* __restrict__ bnb,
         const float* __restrict__ bnm, const float* __restrict__ bnv,
         float* __restrict__ outf, h16* __restrict__ oh,
         int K, int N, float mult)
{
    extern __shared__ __align__(16) h16 smb[];
    const uint32_t s0u = smem_u32(smb);

    const int tid = threadIdx.x;
    const int wid = tid >> 5, l = tid & 31;
    const int wm = wid & 3, wn = wid >> 2;    // warp tile: rows wm*32, cols wn*64
    const int t0 = blockIdx.y * 128;
    const int o0 = blockIdx.x * 128;

    float acc[2][8][4];
#pragma unroll
    for (int f = 0; f < 2; f++)
#pragma unroll
        for (int g = 0; g < 8; g++)
#pragma unroll
            for (int i = 0; i < 4; i++) acc[f][g][i] = 0.f;

    const int arow = l & 15;
    const int acol = (l >> 4) * 8;
    const int brow = ((l >> 4) << 3) + (l & 7);
    const int bcol = ((l >> 3) & 1) * 8;

    const int nch = K / KC;
    gemm_load_stage(A, W, t0, o0, K, 0, s0u);

    for (int ch = 0; ch < nch; ++ch) {
        const int buf = ch & 1;
        __syncthreads();
        if (ch + 1 < nch) {
            gemm_load_stage(A, W, t0, o0, K, (ch+1)*KC,
                            s0u + (uint32_t)(buf ^ 1) * STAGE_B);
            CP_WAIT1();
        } else {
            CP_WAIT0();
        }
        __syncthreads();

        const uint32_t sa = s0u + (uint32_t)buf * STAGE_B;
#pragma unroll
        for (int kk = 0; kk < 2; ++kk) {
            const int k0 = kk * 16;
            uint32_t af[2][4], bf[4][4];
#pragma unroll
            for (int f = 0; f < 2; ++f) {
                uint32_t off = (uint32_t)(((wm*32 + f*16 + arow)*ASTR + k0 + acol) * 2);
                ldsm4(af[f], sa + off);
            }
#pragma unroll
            for (int gp = 0; gp < 4; ++gp) {
                uint32_t off = (uint32_t)(((wn*64 + gp*16 + brow)*ASTR + k0 + bcol) * 2);
                ldsm4(bf[gp], sa + TILE_B + off);
            }
#pragma unroll
            for (int f = 0; f < 2; ++f)
#pragma unroll
                for (int gp = 0; gp < 4; ++gp) {
                    mma16816(acc[f][2*gp],   af[f], bf[gp][0], bf[gp][1]);
                    mma16816(acc[f][2*gp+1], af[f], bf[gp][2], bf[gp][3]);
                }
        }
    }

    // ---- epilogue ----
    const int row_in = l >> 2, col_in = (l & 3) * 2;
#pragma unroll
    for (int f = 0; f < 2; ++f) {
        const int tb = t0 + wm*32 + f*16 + row_in;
#pragma unroll
        for (int g = 0; g < 8; ++g) {
            const int o = o0 + wn*64 + g*8 + col_in;
#pragma unroll
            for (int hhalf = 0; hhalf < 2; ++hhalf) {
                const int t = tb + hhalf*8;
                const float c0 = acc[f][g][hhalf*2 + 0];
                const float c1 = acc[f][g][hhalf*2 + 1];
                if (MODE == 0) {
                    float v0 = (c0 + bias[o]) * mult;
                    float v1 = (c1 + bias[o+1]) * mult;
                    *(uint32_t*)&oh[(size_t)t*N + o] =
                        pack_h2(__float2half_rn(v0), __float2half_rn(v1));
                } else if (MODE == 1) {
#pragma unroll
                    for (int u = 0; u < 2; ++u) {
                        int oo = o + u;
                        size_t idx = (size_t)t*C_DIM + oo;
                        float val = (u ? c1 : c0) + bias[oo] + res[idx];
                        outf[idx] = val;
                        float inv = rsqrtf(bnv[oo] + BN_EPS);
                        float hb = (val - bnm[oo]) * inv * bng[oo] + bnb[oo];
                        oh[idx] = __float2half_rn(hb);
                    }
                } else if (MODE == 2) {
#pragma unroll
                    for (int u = 0; u < 2; ++u) {
                        int oo = o + u;
                        float val = (u ? c1 : c0) + bias[oo];
                        float ge = 0.5f * val * (1.0f + erff(val * 0.7071067811865475f));
                        oh[(size_t)t*N + oo] = __float2half_rn(ge);
                    }
                } else if (MODE == 3) { // NCHW final
                    const int bb2 = t / NPIX;
                    const int nn  = t - bb2 * NPIX;
#pragma unroll
                    for (int u = 0; u < 2; ++u) {
                        int oo = o + u;
                        float val = (u ? c1 : c0) + bias[oo] + res[(size_t)t*C_DIM + oo];
                        outf[((size_t)bb2*C_DIM + oo)*NPIX + nn] = val;
                    }
                } else { // MODE 4: V head-transposed [b][h][d][n]
                    const int bb2 = t / NPIX;
                    const int nn  = t - bb2 * NPIX;
#pragma unroll
                    for (int u = 0; u < 2; ++u) {
                        int oo = o + u;
                        int hh2 = oo / HDIM, dd = oo - hh2*HDIM;
                        float val = (u ? c1 : c0) + bias[oo];
                        size_t dst = ((size_t)((bb2*HEADS + hh2)*HDIM + dd))*NPIX + nn;
                        oh[dst] = __float2half_rn(val);
                    }
                }
            }
        }
    }
}

// ======================= flash-style fp16 mma attention (cp.async K/V pipeline) =======================
#define AQ_STR 56
#define AK_STR 56
#define AV_STR 72
#define K_STAGE_ELE (64*AK_STR)   // 3584
#define V_STAGE_ELE (48*AV_STR)   // 3456
#define ATTN_SMEM ((128*AQ_STR + 2*K_STAGE_ELE + 2*V_STAGE_ELE) * 2)   // 42496 B
#define NBLK ((NPIX + 63) / 64)   // 13

__device__ __forceinline__ void attn_load_kv(
    const h16* __restrict__ Kf, const h16* __restrict__ Vtf,
    int b, int h, int n0, uint32_t k_u, uint32_t v_u)
{
    int tid = threadIdx.x;
    for (int idx = tid; idx < 64*6; idx += 256) {
        int r = idx / 6, cs = idx % 6;
        int t = b*NPIX + min(n0 + r, NPIX - 1);
        cp16(k_u + (uint32_t)((r*AK_STR + cs*8) * 2), Kf + (size_t)t*C_DIM + h*HDIM + cs*8);
    }
    for (int idx = tid; idx < 48*8; idx += 256) {
        int r = idx / 8, cs = idx % 8;
        size_t so = ((size_t)((b*HEADS + h)*HDIM + r))*NPIX + n0 + cs*8;
        cp16(v_u + (uint32_t)((r*AV_STR + cs*8) * 2), Vtf + so);
    }
    CP_COMMIT();
}

__global__ void __launch_bounds__(256)
attn_mma(const h16* __restrict__ Qf, const h16* __restrict__ Kf,
         const h16* __restrict__ Vtf, h16* __restrict__ AOf)
{
    extern __shared__ __align__(16) h16 sm_[];
    h16* sQ = sm_;
    h16* sK = sQ + 128*AQ_STR;       // [2 stages]
    h16* sV = sK + 2*K_STAGE_ELE;    // [2 stages]

    const int tid = threadIdx.x, w = tid >> 5, ln = tid & 31;
    const int qb = blockIdx.x, h = blockIdx.y, b = blockIdx.z;
    const int q0 = qb * 128;

    uint32_t kst[2], vst[2];
#pragma unroll
    for (int s = 0; s < 2; s++) {
        kst[s] = smem_u32(sK + s*K_STAGE_ELE);
        vst[s] = smem_u32(sV + s*V_STAGE_ELE);
    }

    // prefetch K/V block 0 while Q loads
    attn_load_kv(Kf, Vtf, b, h, 0, kst[0], vst[0]);

    // ---- load Q tile (rows clamped to image) ----
    for (int idx = tid; idx < 128*6; idx += 256) {
        int r = idx / 6, cs = idx % 6;
        int t = b*NPIX + min(q0 + r, NPIX - 1);
        *(uint4*)(sQ + r*AQ_STR + cs*8) = *((const uint4*)(Qf + (size_t)t*C_DIM + h*HDIM) + cs);
    }
    __syncthreads();

    // ---- Q fragments (persistent) ----
    const int arow = ln & 15, acol = (ln >> 4) * 8;
    const int brow = ((ln >> 4) << 3) + (ln & 7), bcol = ((ln >> 3) & 1) * 8;
    uint32_t qf[3][4];
    {
        const uint32_t qbase = smem_u32(sQ);
#pragma unroll
        for (int kc = 0; kc < 3; kc++) {
            uint32_t off = (uint32_t)(((w*16 + arow)*AQ_STR + kc*16 + acol) * 2);
            ldsm4(qf[kc], qbase + off);
        }
    }

    float rm0 = -1e30f, rm1 = -1e30f;   // running max (rows ln/4, ln/4+8)
    float rl0 = 0.f,    rl1 = 0.f;      // running sum
    float O[6][4];
#pragma unroll
    for (int j = 0; j < 6; j++)
#pragma unroll
        for (int i = 0; i < 4; i++) O[j][i] = 0.f;

    for (int it = 0; it < NBLK; ++it) {
        const int buf = it & 1;
        const int n0 = it * 64;
        __syncthreads();
        if (it + 1 < NBLK) {
            attn_load_kv(Kf, Vtf, b, h, (it+1)*64, kst[buf^1], vst[buf^1]);
            CP_WAIT1();
        } else {
            CP_WAIT0();
        }
        __syncthreads();

        // ---- S = Q K^T (single product) ----
        float s[8][4];
#pragma unroll
        for (int j = 0; j < 8; j++)
#pragma unroll
            for (int i = 0; i < 4; i++) s[j][i] = 0.f;

#pragma unroll
        for (int kc = 0; kc < 3; kc++) {
#pragma unroll
            for (int g = 0; g < 4; g++) {
                uint32_t off = (uint32_t)(((g*16 + brow)*AK_STR + kc*16 + bcol) * 2);
                uint32_t k4[4];
                ldsm4(k4, kst[buf] + off);
                mma16816(s[2*g],   qf[kc], k4[0], k4[1]);
                mma16816(s[2*g+1], qf[kc], k4[2], k4[3]);
            }
        }

        // ---- mask tail keys ----
        if (n0 + 64 > NPIX) {
            int c2 = 2*(ln & 3);
#pragma unroll
            for (int j = 0; j < 8; j++) {
                int col = n0 + 8*j + c2;
                if (col >= NPIX) { s[j][0] = s[j][1] = s[j][2] = s[j][3] = -1e30f; }
            }
        }

        // ---- online softmax ----
        float bm0 = -1e30f, bm1 = -1e30f;
#pragma unroll
        for (int j = 0; j < 8; j++) {
            bm0 = fmaxf(bm0, fmaxf(s[j][0], s[j][1]));
            bm1 = fmaxf(bm1, fmaxf(s[j][2], s[j][3]));
        }
        bm0 = fmaxf(bm0, __shfl_xor_sync(0xffffffffu, bm0, 1));
        bm0 = fmaxf(bm0, __shfl_xor_sync(0xffffffffu, bm0, 2));
        bm1 = fmaxf(bm1, __shfl_xor_sync(0xffffffffu, bm1, 1));
        bm1 = fmaxf(bm1, __shfl_xor_sync(0xffffffffu, bm1, 2));
        float nm0 = fmaxf(rm0, bm0), nm1 = fmaxf(rm1, bm1);
        float sc0 = __expf(rm0 - nm0), sc1 = __expf(rm1 - nm1);
        rm0 = nm0; rm1 = nm1;
        float bs0 = 0.f, bs1 = 0.f;
#pragma unroll
        for (int j = 0; j < 8; j++) {
            s[j][0] = __expf(s[j][0] - nm0);
            s[j][1] = __expf(s[j][1] - nm0);
            s[j][2] = __expf(s[j][2] - nm1);
            s[j][3] = __expf(s[j][3] - nm1);
            bs0 += s[j][0] + s[j][1];
            bs1 += s[j][2] + s[j][3];
        }
        bs0 += __shfl_xor_sync(0xffffffffu, bs0, 1);
        bs0 += __shfl_xor_sync(0xffffffffu, bs0, 2);
        bs1 += __shfl_xor_sync(0xffffffffu, bs1, 1);
        bs1 += __shfl_xor_sync(0xffffffffu, bs1, 2);
        rl0 = rl0*sc0 + bs0;
        rl1 = rl1*sc1 + bs1;
#pragma unroll
        for (int j = 0; j < 6; j++) {
            O[j][0] *= sc0; O[j][1] *= sc0;
            O[j][2] *= sc1; O[j][3] *= sc1;
        }

        // ---- O += P V (single product; P packed from S regs) ----
#pragma unroll
        for (int kc = 0; kc < 4; kc++) {
            uint32_t ph[4];
            ph[0] = pack_h2(__float2half_rn(s[2*kc][0]),   __float2half_rn(s[2*kc][1]));
            ph[1] = pack_h2(__float2half_rn(s[2*kc][2]),   __float2half_rn(s[2*kc][3]));
            ph[2] = pack_h2(__float2half_rn(s[2*kc+1][0]), __float2half_rn(s[2*kc+1][1]));
            ph[3] = pack_h2(__float2half_rn(s[2*kc+1][2]), __float2half_rn(s[2*kc+1][3]));
#pragma unroll
            for (int dg = 0; dg < 3; dg++) {
                uint32_t off = (uint32_t)(((dg*16 + brow)*AV_STR + kc*16 + bcol) * 2);
                uint32_t v4[4];
                ldsm4(v4, vst[buf] + off);
                mma16816(O[2*dg],   ph, v4[0], v4[1]);
                mma16816(O[2*dg+1], ph, v4[2], v4[3]);
            }
        }
    }

    // ---- epilogue: normalize + store fp16 ----
    float inv0 = 1.f / rl0, inv1 = 1.f / rl1;
    int r0 = q0 + w*16 + (ln >> 2);
    int r1 = r0 + 8;
    int cbase = h*HDIM + 2*(ln & 3);
#pragma unroll
    for (int jn = 0; jn < 6; jn++) {
        int c = cbase + 8*jn;
        if (r0 < NPIX) {
            size_t idx = (size_t)(b*NPIX + r0)*C_DIM + c;
            *(uint32_t*)&AOf[idx] =
                pack_h2(__float2half_rn(O[jn][0]*inv0), __float2half_rn(O[jn][1]*inv0));
        }
        if (r1 < NPIX) {
            size_t idx = (size_t)(b*NPIX + r1)*C_DIM + c;
            *(uint32_t*)&AOf[idx] =
                pack_h2(__float2half_rn(O[jn][2]*inv1), __float2half_rn(O[jn][3]*inv1));
        }
    }
}

// ---------------- host ----------------
extern "C" void kernel_launch(void* const* d_in, const int* in_sizes, int n_in,
                              void* d_out, int out_size)
{
    const float* x       = (const float*)d_in[0];
    const float* local_w = (const float*)d_in[1];
    const float* local_b = (const float*)d_in[2];
    const float* bn1_g   = (const float*)d_in[3];
    const float* bn1_b   = (const float*)d_in[4];
    const float* bn1_m   = (const float*)d_in[5];
    const float* bn1_v   = (const float*)d_in[6];
    const float* q_w     = (const float*)d_in[7];
    const float* q_b     = (const float*)d_in[8];
    const float* k_w     = (const float*)d_in[9];
    const float* k_b     = (const float*)d_in[10];
    const float* v_w     = (const float*)d_in[11];
    const float* v_b     = (const float*)d_in[12];
    const float* proj_w  = (const float*)d_in[13];
    const float* proj_b  = (const float*)d_in[14];
    const float* ffn1_w  = (const float*)d_in[15];
    const float* ffn1_b  = (const float*)d_in[16];
    const float* ffn2_w  = (const float*)d_in[17];
    const float* ffn2_b  = (const float*)d_in[18];
    const float* bn2_g   = (const float*)d_in[19];
    const float* bn2_b   = (const float*)d_in[20];
    const float* bn2_m   = (const float*)d_in[21];
    const float* bn2_v   = (const float*)d_in[22];

    float *lx, *r;
    h16 *lxf, *qf, *kf, *vtf, *aof, *hf, *f1f;
    h16 *qw, *kw, *vw, *pw, *w1, *w2;
    cudaGetSymbolAddress((void**)&lx,  g_lx);
    cudaGetSymbolAddress((void**)&lxf, g_lxf);
    cudaGetSymbolAddress((void**)&qf,  g_qf);
    cudaGetSymbolAddress((void**)&kf,  g_kf);
    cudaGetSymbolAddress((void**)&vtf, g_vtf);
    cudaGetSymbolAddress((void**)&aof, g_aof);
    cudaGetSymbolAddress((void**)&r,   g_r);
    cudaGetSymbolAddress((void**)&hf,  g_hf);
    cudaGetSymbolAddress((void**)&f1f, g_f1f);
    cudaGetSymbolAddress((void**)&qw,  g_qw);
    cudaGetSymbolAddress((void**)&kw,  g_kw);
    cudaGetSymbolAddress((void**)&vw,  g_vw);
    cudaGetSymbolAddress((void**)&pw,  g_pw);
    cudaGetSymbolAddress((void**)&w1,  g_w1);
    cudaGetSymbolAddress((void**)&w2,  g_w2);

    cudaFuncSetAttribute(gemm_mma<0>, cudaFuncAttributeMaxDynamicSharedMemorySize, GEMM_SMEM);
    cudaFuncSetAttribute(gemm_mma<1>, cudaFuncAttributeMaxDynamicSharedMemorySize, GEMM_SMEM);
    cudaFuncSetAttribute(gemm_mma<2>, cudaFuncAttributeMaxDynamicSharedMemorySize, GEMM_SMEM);
    cudaFuncSetAttribute(gemm_mma<3>, cudaFuncAttributeMaxDynamicSharedMemorySize, GEMM_SMEM);
    cudaFuncSetAttribute(gemm_mma<4>, cudaFuncAttributeMaxDynamicSharedMemorySize, GEMM_SMEM);
    cudaFuncSetAttribute(attn_mma,    cudaFuncAttributeMaxDynamicSharedMemorySize, ATTN_SMEM);

    // 0. all weight conversions in one launch
    cvt_all_kernel<<<(4*NW + 2*NF + 255)/256, 256>>>(
        q_w, qw, k_w, kw, v_w, vw, proj_w, pw, ffn1_w, w1, ffn2_w, w2);

    // 1. fused depthwise conv + BN1 + transpose -> token-major (+ fp16)
    conv_tokens_kernel<<<dim3(25, 12, BATCH), dim3(32, 8)>>>(
        x, local_w, local_b, bn1_g, bn1_b, bn1_m, bn1_v);

    dim3 g384(3, 98), g1536(12, 98);
    const float scale = 0.14433756729740643f;   // 48^-0.5

    // 2. QKV: Q (scale folded) / K -> [t][c]; V -> [b][h][d][n]
    gemm_mma<0><<<g384, 256, GEMM_SMEM>>>(lxf, qw, q_b, nullptr,
        nullptr, nullptr, nullptr, nullptr, nullptr, qf, C_DIM, C_DIM, scale);
    gemm_mma<0><<<g384, 256, GEMM_SMEM>>>(lxf, kw, k_b, nullptr,
        nullptr, nullptr, nullptr, nullptr, nullptr, kf, C_DIM, C_DIM, 1.0f);
    gemm_mma<4><<<g384, 256, GEMM_SMEM>>>(lxf, vw, v_b, nullptr,
        nullptr, nullptr, nullptr, nullptr, nullptr, vtf, C_DIM, C_DIM, 1.0f);

    // 3. flash attention (fp16 tensor cores, pipelined K/V)
    attn_mma<<<dim3(7, HEADS, BATCH), 256, ATTN_SMEM>>>(qf, kf, vtf, aof);

    // 4. proj + residual(lx) -> r (f32); BN2 -> h (fp16)
    gemm_mma<1><<<g384, 256, GEMM_SMEM>>>(aof, pw, proj_b, lx,
        bn2_g, bn2_b, bn2_m, bn2_v, r, hf, C_DIM, C_DIM, 1.0f);

    // 5. FFN1 + gelu -> f1 (fp16)
    gemm_mma<2><<<g1536, 256, GEMM_SMEM>>>(hf, w1, ffn1_b, nullptr,
        nullptr, nullptr, nullptr, nullptr, nullptr, f1f, C_DIM, FFN_DIM, 1.0f);

    // 6. FFN2 + residual(r), NCHW output
    gemm_mma<3><<<g384, 256, GEMM_SMEM>>>(f1f, w2, ffn2_b, r,
        nullptr, nullptr, nullptr, nullptr, (float*)d_out, nullptr, FFN_DIM, C_DIM, 1.0f);
}